// round 1
// baseline (speedup 1.0000x reference)
#include <cuda_runtime.h>
#include <math.h>

#define BATCH 2
#define LSEQ 4096
#define DMODEL 2048
#define D3 (3*DMODEL)
#define ORDER 64
#define NFFT 8192
#define NHALF 4096
#define FFT_T 512
#define FFT_SMEM ((NFFT + NFFT + NHALF) * (int)sizeof(float2))  // 160 KB

// ---------------------------------------------------------------------------
// Scratch (device globals; no dynamic allocation allowed)
// ---------------------------------------------------------------------------
__device__ float  g_u [(size_t)BATCH*LSEQ*D3];     // in_proj output (B, L, 3D)
__device__ float  g_x0[(size_t)BATCH*DMODEL*LSEQ]; // gate x0 (B, D, L)
__device__ float  g_vg[(size_t)BATCH*DMODEL*LSEQ]; // v * x1  (B, D, L)
__device__ float  g_y [(size_t)BATCH*DMODEL*LSEQ]; // post-conv gated (B, D, L)
__device__ float  g_h [(size_t)LSEQ*ORDER];        // filter MLP hidden (L, 64)
__device__ float  g_k [(size_t)DMODEL*LSEQ];       // filter kernel (D, L)
__device__ float2 g_Kf[(size_t)DMODEL*NFFT];       // FFT(k)/NFFT per channel

// ---------------------------------------------------------------------------
// SGEMM: C[M,N] = A[M,K] * W[N,K]^T + bias.  128x128x8 tile, 8x8 per thread.
// AKM=true : A row-major, K contiguous (A[m*lda + k])
// AKM=false: A column-major within batch   (A[k*lda + m])
// ---------------------------------------------------------------------------
template<bool AKM>
__device__ __forceinline__ void sgemm_body(const float* __restrict__ A,
                                           const float* __restrict__ W,
                                           const float* __restrict__ bias,
                                           float* __restrict__ C,
                                           int lda, int N, int K)
{
    __shared__ float As[8][128];
    __shared__ float Bs[8][128];
    const int tid  = threadIdx.x;
    const int row0 = blockIdx.y * 128;
    const int col0 = blockIdx.x * 128;
    const int tx = tid & 15, ty = tid >> 4;

    float acc[8][8];
#pragma unroll
    for (int i = 0; i < 8; i++)
#pragma unroll
        for (int j = 0; j < 8; j++) acc[i][j] = 0.f;

    for (int k0 = 0; k0 < K; k0 += 8) {
        if (AKM) {
            const float4 a4 = *(const float4*)(A + (size_t)(row0 + (tid >> 1)) * lda + k0 + (tid & 1) * 4);
            const int m = tid >> 1, kk = (tid & 1) * 4;
            As[kk+0][m] = a4.x; As[kk+1][m] = a4.y; As[kk+2][m] = a4.z; As[kk+3][m] = a4.w;
        } else {
            const float4 a4 = *(const float4*)(A + (size_t)(k0 + (tid >> 5)) * lda + row0 + (tid & 31) * 4);
            *(float4*)&As[tid >> 5][(tid & 31) * 4] = a4;
        }
        {
            const float4 b4 = *(const float4*)(W + (size_t)(col0 + (tid >> 1)) * K + k0 + (tid & 1) * 4);
            const int n = tid >> 1, kk = (tid & 1) * 4;
            Bs[kk+0][n] = b4.x; Bs[kk+1][n] = b4.y; Bs[kk+2][n] = b4.z; Bs[kk+3][n] = b4.w;
        }
        __syncthreads();
#pragma unroll
        for (int kk = 0; kk < 8; kk++) {
            float a[8], b[8];
            *(float4*)(a)     = *(const float4*)&As[kk][ty * 8];
            *(float4*)(a + 4) = *(const float4*)&As[kk][ty * 8 + 4];
            *(float4*)(b)     = *(const float4*)&Bs[kk][tx * 8];
            *(float4*)(b + 4) = *(const float4*)&Bs[kk][tx * 8 + 4];
#pragma unroll
            for (int i = 0; i < 8; i++)
#pragma unroll
                for (int j = 0; j < 8; j++)
                    acc[i][j] = fmaf(a[i], b[j], acc[i][j]);
        }
        __syncthreads();
    }
#pragma unroll
    for (int i = 0; i < 8; i++) {
        const size_t r = (size_t)(row0 + ty * 8 + i);
#pragma unroll
        for (int j = 0; j < 8; j += 4) {
            const int c = col0 + tx * 8 + j;
            float4 v;
            v.x = acc[i][j+0] + bias[c+0];
            v.y = acc[i][j+1] + bias[c+1];
            v.z = acc[i][j+2] + bias[c+2];
            v.w = acc[i][j+3] + bias[c+3];
            *(float4*)(C + r * (size_t)N + c) = v;
        }
    }
}

__global__ void __launch_bounds__(256)
gemm_in_kernel(const float* __restrict__ x, const float* __restrict__ w,
               const float* __restrict__ b)
{
    // M = B*L = 8192, N = 3D = 6144, K = D = 2048
    sgemm_body<true>(x, w, b, g_u, DMODEL, D3, DMODEL);
}

__global__ void __launch_bounds__(256)
gemm_out_kernel(const float* __restrict__ w, const float* __restrict__ b,
                float* __restrict__ out)
{
    const int z = blockIdx.z;  // batch
    sgemm_body<false>(g_y + (size_t)z * DMODEL * LSEQ, w, b,
                      out + (size_t)z * LSEQ * DMODEL, LSEQ, DMODEL, DMODEL);
}

// ---------------------------------------------------------------------------
// Short conv (depthwise K=3, causal) + transpose to (B,D,L) + gating v*x1
// uc[c,l] = w0*u[l-2,c] + w1*u[l-1,c] + w2*u[l,c] + sb[c]
// ---------------------------------------------------------------------------
__global__ void __launch_bounds__(256)
shortconv_kernel(const float* __restrict__ sw, const float* __restrict__ sb)
{
    __shared__ float su[3][34][33];
    const int b = blockIdx.z, l0 = blockIdx.x * 32, d0 = blockIdx.y * 32;
    const int tx = threadIdx.x, ty = threadIdx.y;

#pragma unroll
    for (int g = 0; g < 3; g++)
        for (int li = ty; li < 34; li += 8) {
            const int l = l0 + li - 2;
            su[g][li][tx] = (l >= 0)
                ? g_u[((size_t)b * LSEQ + l) * D3 + g * DMODEL + d0 + tx] : 0.f;
        }
    __syncthreads();

    const int l = l0 + tx;
    for (int di = ty; di < 32; di += 8) {
        const int d = d0 + di;
        float r[3];
#pragma unroll
        for (int g = 0; g < 3; g++) {
            const int c = g * DMODEL + d;
            r[g] = sw[c*3+0] * su[g][tx][di]
                 + sw[c*3+1] * su[g][tx+1][di]
                 + sw[c*3+2] * su[g][tx+2][di]
                 + sb[c];
        }
        const size_t o = ((size_t)b * DMODEL + d) * LSEQ + l;
        g_x0[o] = r[0];
        g_vg[o] = r[1] * r[2];
    }
}

// ---------------------------------------------------------------------------
// Filter MLP hidden state h (L, 64)
// ---------------------------------------------------------------------------
__global__ void __launch_bounds__(256)
filter_h_kernel(const float* __restrict__ w0, const float* __restrict__ b0,
                const float* __restrict__ freq,
                const float* __restrict__ w1, const float* __restrict__ b1,
                const float* __restrict__ w2, const float* __restrict__ b2)
{
    __shared__ float ws[ORDER][ORDER + 1];
    __shared__ float h1[4][ORDER + 1];
    const int o  = threadIdx.x;          // 0..63
    const int lq = threadIdx.y;          // 0..3
    const int l  = blockIdx.x * 4 + lq;
    const int tid = lq * ORDER + o;

    const float t   = (float)l / (float)(LSEQ - 1);
    const float wl  = 2.f * 3.14159265358979323846f * (float)l / (float)LSEQ;
    const float ang = 1e-4f * wl;
    const float z1 = cosf(ang), z2 = -sinf(ang);
    const float fr = freq[o];
    float v = t * w0[o*3+0] + z1 * w0[o*3+1] + z2 * w0[o*3+2] + b0[o];
    h1[lq][o] = sinf(fr * v);
    for (int i = tid; i < ORDER * ORDER; i += 256) ws[i >> 6][i & 63] = w1[i];
    __syncthreads();

    float s = b1[o];
#pragma unroll 8
    for (int j = 0; j < ORDER; j++) s = fmaf(ws[o][j], h1[lq][j], s);
    const float h2v = sinf(fr * s);
    __syncthreads();

    h1[lq][o] = h2v;
    for (int i = tid; i < ORDER * ORDER; i += 256) ws[i >> 6][i & 63] = w2[i];
    __syncthreads();

    s = b2[o];
#pragma unroll 8
    for (int j = 0; j < ORDER; j++) s = fmaf(ws[o][j], h1[lq][j], s);
    g_h[(size_t)l * ORDER + o] = sinf(fr * s);
}

// ---------------------------------------------------------------------------
// k[d,l] = dot(w3[d], h[l]) * exp(-t_l * |delta_d|)
// ---------------------------------------------------------------------------
__global__ void __launch_bounds__(256)
filter_k_kernel(const float* __restrict__ w3)
{
    __shared__ float hs[32][ORDER + 1];
    const int l0 = blockIdx.x * 32, d0 = blockIdx.y * 32;
    const int tx = threadIdx.x, ty = threadIdx.y;

    for (int i = ty; i < 32; i += 8) {
        hs[i][tx]      = g_h[(size_t)(l0 + i) * ORDER + tx];
        hs[i][tx + 32] = g_h[(size_t)(l0 + i) * ORDER + tx + 32];
    }
    __syncthreads();

    const int l = l0 + tx;
    const float t = (float)l / (float)(LSEQ - 1);
    const float min_decay = -4.60517018598809136804f / 1.5f;
    const float max_decay = -4.60517018598809136804f / 0.3f;
    for (int di = ty; di < 32; di += 8) {
        const int d = d0 + di;
        float s = 0.f;
#pragma unroll 8
        for (int j = 0; j < ORDER; j++)
            s = fmaf(w3[(size_t)d * ORDER + j], hs[tx][j], s);
        const float delta = min_decay + (max_decay - min_decay) * (float)d / (float)(DMODEL - 1);
        g_k[(size_t)d * LSEQ + l] = s * expf(-t * fabsf(delta));
    }
}

// ---------------------------------------------------------------------------
// Stockham radix-2 DIF FFT, N=8192 complex, in shared memory (natural order out)
// ---------------------------------------------------------------------------
__device__ __forceinline__ void fft_init_tw(float2* tw)
{
    for (int i = threadIdx.x; i < NHALF; i += FFT_T) {
        float s, c;
        sincosf(-3.14159265358979323846f * (float)i / (float)NHALF, &s, &c);
        tw[i] = make_float2(c, s);
    }
}

__device__ __forceinline__ float2* fft8192(float2* srcBuf, float2* dstBuf, const float2* tw)
{
    float2* src = srcBuf;
    float2* dst = dstBuf;
#pragma unroll 1
    for (int s = 0; s < 13; s++) {
        const int m = 1 << s;
        __syncthreads();
#pragma unroll 1
        for (int i = threadIdx.x; i < NHALF; i += FFT_T) {
            const int k  = i & (m - 1);
            const int jm = i - k;           // j*m
            const float2 c0 = src[i];
            const float2 c1 = src[i + NHALF];
            const float2 w  = tw[jm];
            const float dx = c0.x - c1.x, dy = c0.y - c1.y;
            dst[2*jm + k]     = make_float2(c0.x + c1.x, c0.y + c1.y);
            dst[2*jm + k + m] = make_float2(dx * w.x - dy * w.y, dx * w.y + dy * w.x);
        }
        float2* t = src; src = dst; dst = t;
    }
    __syncthreads();
    return src;  // result buffer
}

__global__ void fftk_kernel()
{
    extern __shared__ float2 smem_fft[];
    float2* bufA = smem_fft;
    float2* bufB = bufA + NFFT;
    float2* tw   = bufB + NFFT;
    fft_init_tw(tw);

    const int d = blockIdx.x;
    const float* kr = g_k + (size_t)d * LSEQ;
    for (int i = threadIdx.x; i < LSEQ; i += FFT_T) {
        bufA[i]        = make_float2(kr[i], 0.f);
        bufA[i + LSEQ] = make_float2(0.f, 0.f);
    }
    float2* out = fft8192(bufA, bufB, tw);
    const float sc = 1.0f / (float)NFFT;
    for (int i = threadIdx.x; i < NFFT; i += FFT_T)
        g_Kf[(size_t)d * NFFT + i] = make_float2(out[i].x * sc, out[i].y * sc);
}

// Fused: FFT(vg) -> *K_f -> inverse FFT (conjugation trick) -> +bias -> *x0
__global__ void fftconv_kernel(const float* __restrict__ fbias)
{
    extern __shared__ float2 smem_fft[];
    float2* bufA = smem_fft;
    float2* bufB = bufA + NFFT;
    float2* tw   = bufB + NFFT;
    fft_init_tw(tw);

    const int bd = blockIdx.x;            // b*D + d
    const int d  = bd & (DMODEL - 1);
    const float* vr = g_vg + (size_t)bd * LSEQ;

    for (int i = threadIdx.x; i < LSEQ; i += FFT_T) {
        bufA[i]        = make_float2(vr[i], 0.f);
        bufA[i + LSEQ] = make_float2(0.f, 0.f);
    }
    float2* U     = fft8192(bufA, bufB, tw);
    float2* other = (U == bufA) ? bufB : bufA;

    const float2* kf = g_Kf + (size_t)d * NFFT;
    for (int i = threadIdx.x; i < NFFT; i += FFT_T) {
        const float2 u = U[i];
        const float2 k = kf[i];
        // Z = U * K_f ; store conj(Z) so that FFT gives the unscaled inverse
        other[i] = make_float2(u.x * k.x - u.y * k.y, -(u.x * k.y + u.y * k.x));
    }
    float2* out = fft8192(other, U, tw);

    const float fb = fbias[d];
    for (int i = threadIdx.x; i < LSEQ; i += FFT_T) {
        const size_t o = (size_t)bd * LSEQ + i;
        g_y[o] = (out[i].x + vr[i] * fb) * g_x0[o];
    }
}

// ---------------------------------------------------------------------------
// Launch
// ---------------------------------------------------------------------------
extern "C" void kernel_launch(void* const* d_in, const int* in_sizes, int n_in,
                              void* d_out, int out_size)
{
    (void)in_sizes; (void)n_in; (void)out_size;
    const float* x     = (const float*)d_in[0];
    const float* ipw   = (const float*)d_in[1];
    const float* ipb   = (const float*)d_in[2];
    const float* sw    = (const float*)d_in[3];
    const float* sb    = (const float*)d_in[4];
    const float* w0    = (const float*)d_in[5];
    const float* b0    = (const float*)d_in[6];
    const float* freq  = (const float*)d_in[7];
    const float* w1    = (const float*)d_in[8];
    const float* b1    = (const float*)d_in[9];
    const float* w2    = (const float*)d_in[10];
    const float* b2    = (const float*)d_in[11];
    const float* w3    = (const float*)d_in[12];
    const float* fbias = (const float*)d_in[13];
    const float* opw   = (const float*)d_in[14];
    const float* opb   = (const float*)d_in[15];
    float* out = (float*)d_out;

    cudaFuncSetAttribute(fftk_kernel,    cudaFuncAttributeMaxDynamicSharedMemorySize, FFT_SMEM);
    cudaFuncSetAttribute(fftconv_kernel, cudaFuncAttributeMaxDynamicSharedMemorySize, FFT_SMEM);

    // 1) in_proj GEMM: (8192 x 6144 x 2048)
    gemm_in_kernel<<<dim3(D3/128, (BATCH*LSEQ)/128), 256>>>(x, ipw, ipb);

    // 2) short conv + transpose + gate
    shortconv_kernel<<<dim3(LSEQ/32, DMODEL/32, BATCH), dim3(32, 8)>>>(sw, sb);

    // 3) filter MLP
    filter_h_kernel<<<LSEQ/4, dim3(ORDER, 4)>>>(w0, b0, freq, w1, b1, w2, b2);
    filter_k_kernel<<<dim3(LSEQ/32, DMODEL/32), dim3(32, 8)>>>(w3);

    // 4) FFT of filter k (scaled by 1/N)
    fftk_kernel<<<DMODEL, FFT_T, FFT_SMEM>>>();

    // 5) fused FFT conv + bias + output gate
    fftconv_kernel<<<BATCH*DMODEL, FFT_T, FFT_SMEM>>>(fbias);

    // 6) out_proj GEMM: per-batch (4096 x 2048 x 2048), A column-major
    gemm_out_kernel<<<dim3(DMODEL/128, LSEQ/128, BATCH), 256>>>(opw, opb, out);
}

// round 3
// speedup vs baseline: 2.0034x; 2.0034x over previous
#include <cuda_runtime.h>
#include <cuda_bf16.h>
#include <math.h>
#include <stdint.h>

#define BATCH 2
#define LSEQ 4096
#define DMODEL 2048
#define D3 (3*DMODEL)
#define ORDER 64
#define NFFT 8192
#define NHALF 4096
#define FFT_T 512
#define FFT_SMEM ((NFFT + NFFT + NHALF) * (int)sizeof(float2))  // 160 KB

// ---------------------------------------------------------------------------
// Scratch (device globals; no dynamic allocation allowed)
// ---------------------------------------------------------------------------
__device__ float  g_u [(size_t)BATCH*LSEQ*D3];     // in_proj output (B, L, 3D)
__device__ float  g_x0[(size_t)BATCH*DMODEL*LSEQ]; // gate x0 (B, D, L)
__device__ float  g_vg[(size_t)BATCH*DMODEL*LSEQ]; // v * x1  (B, D, L)
__device__ float  g_y [(size_t)BATCH*DMODEL*LSEQ]; // post-conv gated (B, D, L)
__device__ float  g_h [(size_t)LSEQ*ORDER];        // filter MLP hidden (L, 64)
__device__ float  g_k [(size_t)DMODEL*LSEQ];       // filter kernel (D, L)
__device__ float2 g_Kf[(size_t)DMODEL*NFFT];       // FFT(k)/NFFT per channel

// bf16 split buffers (hi/lo error compensation)
__device__ __nv_bfloat16 g_ah [(size_t)BATCH*LSEQ*DMODEL]; // A hi (x, then y^T)
__device__ __nv_bfloat16 g_al [(size_t)BATCH*LSEQ*DMODEL]; // A lo
__device__ __nv_bfloat16 g_w1h[(size_t)D3*DMODEL];
__device__ __nv_bfloat16 g_w1l[(size_t)D3*DMODEL];
__device__ __nv_bfloat16 g_w2h[(size_t)DMODEL*DMODEL];
__device__ __nv_bfloat16 g_w2l[(size_t)DMODEL*DMODEL];

// ---------------------------------------------------------------------------
// Warp-MMA GEMM: C[M,N] = (Ah+Al)[M,K] * (Wh+Wl)[N,K]^T + bias
// mma.sync m16n8k16 bf16, ldmatrix, 4-stage cp.async pipeline.
// Block 128x128, 8 warps (warp tile 32x64), K-chunk 32.
// ---------------------------------------------------------------------------
#define GK_CHUNK 32
#define ROWPAD 40                       // 32 bf16 cols padded to 40 (80 B)
#define ST_ELEMS (128*ROWPAD)           // per array per stage (bf16 elems)
#define STAGE_ELEMS (4*ST_ELEMS)        // Ah | Al | Bh | Bl
#define NSTAGE 4
#define GM_SMEM (NSTAGE*STAGE_ELEMS*2)  // 163840 B

__device__ __forceinline__ void cpa16(uint32_t s, const void* g) {
    asm volatile("cp.async.cg.shared.global [%0], [%1], 16;" :: "r"(s), "l"(g));
}
#define CP_COMMIT() asm volatile("cp.async.commit_group;" ::: "memory")
#define CP_WAIT2()  asm volatile("cp.async.wait_group 2;" ::: "memory")

#define LDSM_X4(r, addr) \
    asm volatile("ldmatrix.sync.aligned.m8n8.x4.shared.b16 {%0,%1,%2,%3}, [%4];" \
        : "=r"((r)[0]), "=r"((r)[1]), "=r"((r)[2]), "=r"((r)[3]) : "r"(addr))

#define MMA16816(c, a, b) \
    asm volatile("mma.sync.aligned.m16n8k16.row.col.f32.bf16.bf16.f32 " \
        "{%0,%1,%2,%3}, {%4,%5,%6,%7}, {%8,%9}, {%0,%1,%2,%3};" \
        : "+f"((c)[0]), "+f"((c)[1]), "+f"((c)[2]), "+f"((c)[3]) \
        : "r"((a)[0]), "r"((a)[1]), "r"((a)[2]), "r"((a)[3]), \
          "r"((b)[0]), "r"((b)[1]))

__global__ void __launch_bounds__(256)
gemm_tc_kernel(const __nv_bfloat16* __restrict__ Ah, const __nv_bfloat16* __restrict__ Al,
               const __nv_bfloat16* __restrict__ Wh, const __nv_bfloat16* __restrict__ Wl,
               const float* __restrict__ bias, float* __restrict__ C,
               int Ntot, int K, size_t strideA, size_t strideC)
{
    extern __shared__ char smem[];
    __nv_bfloat16* sm = (__nv_bfloat16*)smem;
    const uint32_t sbase = (uint32_t)__cvta_generic_to_shared(smem);
    const int tid  = threadIdx.x;
    const int lane = tid & 31;
    const int wid  = tid >> 5;
    const int wm   = wid & 3;            // 0..3 -> m offset wm*32
    const int wn   = wid >> 2;           // 0..1 -> n offset wn*64

    const int z = blockIdx.z;
    const __nv_bfloat16* Ahb = Ah + (size_t)z * strideA;
    const __nv_bfloat16* Alb = Al + (size_t)z * strideA;
    float* Cb = C + (size_t)z * strideC;

    const int col0 = blockIdx.x * 128;
    const int row0 = blockIdx.y * 128;
    const int nchunk = K / GK_CHUNK;

    float acc[2][8][4];
#pragma unroll
    for (int i = 0; i < 2; i++)
#pragma unroll
        for (int j = 0; j < 8; j++)
#pragma unroll
            for (int q = 0; q < 4; q++) acc[i][j][q] = 0.f;

    // stage loader: 512 16B-segments per array, 256 threads -> 2 iters
    auto load_stage = [&](int stage, int k0) {
        const uint32_t sb = sbase + (uint32_t)(stage * STAGE_ELEMS) * 2;
#pragma unroll
        for (int i = 0; i < 2; i++) {
            const int seg = tid + i * 256;
            const int r = seg >> 2, cs = seg & 3;
            const size_t ga = (size_t)(row0 + r) * K + k0 + cs * 8;
            const size_t gb = (size_t)(col0 + r) * K + k0 + cs * 8;
            const uint32_t so = (uint32_t)(r * ROWPAD + cs * 8) * 2;
            cpa16(sb + so,                    Ahb + ga);
            cpa16(sb + so + ST_ELEMS*2,      Alb + ga);
            cpa16(sb + so + 2*ST_ELEMS*2,    Wh  + gb);
            cpa16(sb + so + 3*ST_ELEMS*2,    Wl  + gb);
        }
    };

    for (int s = 0; s < 3; s++) { load_stage(s, s * GK_CHUNK); CP_COMMIT(); }

    // ldmatrix lane address components (element offsets within a stage array)
    const int a_row = (lane & 15);            // + wm*32 + mt*16
    const int a_col = (lane >> 4) << 3;       // + kl
    const int b_row = (((lane >> 4) & 1) << 3) + (lane & 7);  // quad>>1 *8 + r  (quad = lane>>3)
    const int b_row2 = (((lane >> 3) & 3) >> 1) * 8 + (lane & 7);
    const int b_col = ((lane >> 3) & 1) << 3; // quad&1 *8 + kl

    for (int c = 0; c < nchunk; c++) {
        CP_WAIT2();
        __syncthreads();
        if (c + 3 < nchunk) load_stage((c + 3) & (NSTAGE - 1), (c + 3) * GK_CHUNK);
        CP_COMMIT();

        const uint32_t stb = sbase + (uint32_t)((c & (NSTAGE - 1)) * STAGE_ELEMS) * 2;
#pragma unroll
        for (int step = 0; step < 2; step++) {
            const int kl = step * 16;
            uint32_t ah[2][4], al[2][4];
#pragma unroll
            for (int mt = 0; mt < 2; mt++) {
                const uint32_t off = (uint32_t)((wm*32 + mt*16 + a_row) * ROWPAD + kl + a_col) * 2;
                LDSM_X4(ah[mt], stb + off);
                LDSM_X4(al[mt], stb + ST_ELEMS*2 + off);
            }
            uint32_t bh[8][2], bl[8][2];
#pragma unroll
            for (int p = 0; p < 4; p++) {
                const uint32_t off = (uint32_t)((wn*64 + p*16 + b_row2) * ROWPAD + kl + b_col) * 2;
                uint32_t t[4];
                LDSM_X4(t, stb + 2*ST_ELEMS*2 + off);
                bh[p*2][0]=t[0]; bh[p*2][1]=t[1]; bh[p*2+1][0]=t[2]; bh[p*2+1][1]=t[3];
                LDSM_X4(t, stb + 3*ST_ELEMS*2 + off);
                bl[p*2][0]=t[0]; bl[p*2][1]=t[1]; bl[p*2+1][0]=t[2]; bl[p*2+1][1]=t[3];
            }
#pragma unroll
            for (int mt = 0; mt < 2; mt++)
#pragma unroll
                for (int nt = 0; nt < 8; nt++) {
                    MMA16816(acc[mt][nt], ah[mt], bh[nt]);
                    MMA16816(acc[mt][nt], ah[mt], bl[nt]);
                    MMA16816(acc[mt][nt], al[mt], bh[nt]);
                }
        }
    }

    // epilogue: c frag thread t: rows t/4, t/4+8; cols (t%4)*2, +1
#pragma unroll
    for (int mt = 0; mt < 2; mt++) {
        const int r0g = row0 + wm*32 + mt*16 + (lane >> 2);
#pragma unroll
        for (int nt = 0; nt < 8; nt++) {
            const int col = col0 + wn*64 + nt*8 + (lane & 3)*2;
            const float b0 = bias[col], b1 = bias[col+1];
            float2 v0 = make_float2(acc[mt][nt][0] + b0, acc[mt][nt][1] + b1);
            float2 v1 = make_float2(acc[mt][nt][2] + b0, acc[mt][nt][3] + b1);
            *(float2*)(Cb + (size_t)r0g      * Ntot + col) = v0;
            *(float2*)(Cb + (size_t)(r0g + 8) * Ntot + col) = v1;
        }
    }
}

// ---------------------------------------------------------------------------
// fp32 -> bf16 hi/lo split (elementwise, float4)
// ---------------------------------------------------------------------------
__global__ void __launch_bounds__(256)
split_kernel(const float4* __restrict__ src, __nv_bfloat162* __restrict__ hi,
             __nv_bfloat162* __restrict__ lo, int n4)
{
    const int i = blockIdx.x * 256 + threadIdx.x;
    if (i >= n4) return;
    const float4 v = src[i];
    __nv_bfloat162 h0 = __floats2bfloat162_rn(v.x, v.y);
    __nv_bfloat162 h1 = __floats2bfloat162_rn(v.z, v.w);
    float2 f0 = __bfloat1622float2(h0);
    float2 f1 = __bfloat1622float2(h1);
    hi[i*2+0] = h0;
    hi[i*2+1] = h1;
    lo[i*2+0] = __floats2bfloat162_rn(v.x - f0.x, v.y - f0.y);
    lo[i*2+1] = __floats2bfloat162_rn(v.z - f1.x, v.w - f1.y);
}

// g_y (B,D,L) -> g_ah/g_al (B,L,D) bf16 split via 32x32 transpose tiles
__global__ void __launch_bounds__(256)
transsplit_kernel()
{
    __shared__ float t[32][33];
    const int b = blockIdx.z, d0 = blockIdx.y * 32, l0 = blockIdx.x * 32;
    const int tx = threadIdx.x, ty = threadIdx.y;
    for (int dy = ty; dy < 32; dy += 8)
        t[dy][tx] = g_y[((size_t)b * DMODEL + d0 + dy) * LSEQ + l0 + tx];
    __syncthreads();
    for (int ly = ty; ly < 32; ly += 8) {
        const float v = t[tx][ly];
        const size_t o = ((size_t)b * LSEQ + l0 + ly) * DMODEL + d0 + tx;
        const __nv_bfloat16 h = __float2bfloat16(v);
        g_ah[o] = h;
        g_al[o] = __float2bfloat16(v - __bfloat162float(h));
    }
}

// ---------------------------------------------------------------------------
// Short conv (depthwise K=3, causal) + transpose to (B,D,L) + gating v*x1
// ---------------------------------------------------------------------------
__global__ void __launch_bounds__(256)
shortconv_kernel(const float* __restrict__ sw, const float* __restrict__ sb)
{
    __shared__ float su[3][34][33];
    const int b = blockIdx.z, l0 = blockIdx.x * 32, d0 = blockIdx.y * 32;
    const int tx = threadIdx.x, ty = threadIdx.y;

#pragma unroll
    for (int g = 0; g < 3; g++)
        for (int li = ty; li < 34; li += 8) {
            const int l = l0 + li - 2;
            su[g][li][tx] = (l >= 0)
                ? g_u[((size_t)b * LSEQ + l) * D3 + g * DMODEL + d0 + tx] : 0.f;
        }
    __syncthreads();

    const int l = l0 + tx;
    for (int di = ty; di < 32; di += 8) {
        const int d = d0 + di;
        float r[3];
#pragma unroll
        for (int g = 0; g < 3; g++) {
            const int c = g * DMODEL + d;
            r[g] = sw[c*3+0] * su[g][tx][di]
                 + sw[c*3+1] * su[g][tx+1][di]
                 + sw[c*3+2] * su[g][tx+2][di]
                 + sb[c];
        }
        const size_t o = ((size_t)b * DMODEL + d) * LSEQ + l;
        g_x0[o] = r[0];
        g_vg[o] = r[1] * r[2];
    }
}

// ---------------------------------------------------------------------------
// Filter MLP hidden state h (L, 64)
// ---------------------------------------------------------------------------
__global__ void __launch_bounds__(256)
filter_h_kernel(const float* __restrict__ w0, const float* __restrict__ b0,
                const float* __restrict__ freq,
                const float* __restrict__ w1, const float* __restrict__ b1,
                const float* __restrict__ w2, const float* __restrict__ b2)
{
    __shared__ float ws[ORDER][ORDER + 1];
    __shared__ float h1[4][ORDER + 1];
    const int o  = threadIdx.x;
    const int lq = threadIdx.y;
    const int l  = blockIdx.x * 4 + lq;
    const int tid = lq * ORDER + o;

    const float t   = (float)l / (float)(LSEQ - 1);
    const float wl  = 2.f * 3.14159265358979323846f * (float)l / (float)LSEQ;
    const float ang = 1e-4f * wl;
    const float z1 = cosf(ang), z2 = -sinf(ang);
    const float fr = freq[o];
    float v = t * w0[o*3+0] + z1 * w0[o*3+1] + z2 * w0[o*3+2] + b0[o];
    h1[lq][o] = sinf(fr * v);
    for (int i = tid; i < ORDER * ORDER; i += 256) ws[i >> 6][i & 63] = w1[i];
    __syncthreads();

    float s = b1[o];
#pragma unroll 8
    for (int j = 0; j < ORDER; j++) s = fmaf(ws[o][j], h1[lq][j], s);
    const float h2v = sinf(fr * s);
    __syncthreads();

    h1[lq][o] = h2v;
    for (int i = tid; i < ORDER * ORDER; i += 256) ws[i >> 6][i & 63] = w2[i];
    __syncthreads();

    s = b2[o];
#pragma unroll 8
    for (int j = 0; j < ORDER; j++) s = fmaf(ws[o][j], h1[lq][j], s);
    g_h[(size_t)l * ORDER + o] = sinf(fr * s);
}

// ---------------------------------------------------------------------------
// k[d,l] = dot(w3[d], h[l]) * exp(-t_l * |delta_d|)
// ---------------------------------------------------------------------------
__global__ void __launch_bounds__(256)
filter_k_kernel(const float* __restrict__ w3)
{
    __shared__ float hs[32][ORDER + 1];
    const int l0 = blockIdx.x * 32, d0 = blockIdx.y * 32;
    const int tx = threadIdx.x, ty = threadIdx.y;

    for (int i = ty; i < 32; i += 8) {
        hs[i][tx]      = g_h[(size_t)(l0 + i) * ORDER + tx];
        hs[i][tx + 32] = g_h[(size_t)(l0 + i) * ORDER + tx + 32];
    }
    __syncthreads();

    const int l = l0 + tx;
    const float t = (float)l / (float)(LSEQ - 1);
    const float min_decay = -4.60517018598809136804f / 1.5f;
    const float max_decay = -4.60517018598809136804f / 0.3f;
    for (int di = ty; di < 32; di += 8) {
        const int d = d0 + di;
        float s = 0.f;
#pragma unroll 8
        for (int j = 0; j < ORDER; j++)
            s = fmaf(w3[(size_t)d * ORDER + j], hs[tx][j], s);
        const float delta = min_decay + (max_decay - min_decay) * (float)d / (float)(DMODEL - 1);
        g_k[(size_t)d * LSEQ + l] = s * expf(-t * fabsf(delta));
    }
}

// ---------------------------------------------------------------------------
// Stockham radix-2 DIF FFT, N=8192 complex, in shared memory
// ---------------------------------------------------------------------------
__device__ __forceinline__ void fft_init_tw(float2* tw)
{
    for (int i = threadIdx.x; i < NHALF; i += FFT_T) {
        float s, c;
        sincosf(-3.14159265358979323846f * (float)i / (float)NHALF, &s, &c);
        tw[i] = make_float2(c, s);
    }
}

__device__ __forceinline__ float2* fft8192(float2* srcBuf, float2* dstBuf, const float2* tw)
{
    float2* src = srcBuf;
    float2* dst = dstBuf;
#pragma unroll 1
    for (int s = 0; s < 13; s++) {
        const int m = 1 << s;
        __syncthreads();
#pragma unroll 1
        for (int i = threadIdx.x; i < NHALF; i += FFT_T) {
            const int k  = i & (m - 1);
            const int jm = i - k;
            const float2 c0 = src[i];
            const float2 c1 = src[i + NHALF];
            const float2 w  = tw[jm];
            const float dx = c0.x - c1.x, dy = c0.y - c1.y;
            dst[2*jm + k]     = make_float2(c0.x + c1.x, c0.y + c1.y);
            dst[2*jm + k + m] = make_float2(dx * w.x - dy * w.y, dx * w.y + dy * w.x);
        }
        float2* t = src; src = dst; dst = t;
    }
    __syncthreads();
    return src;
}

__global__ void fftk_kernel()
{
    extern __shared__ float2 smem_fft[];
    float2* bufA = smem_fft;
    float2* bufB = bufA + NFFT;
    float2* tw   = bufB + NFFT;
    fft_init_tw(tw);

    const int d = blockIdx.x;
    const float* kr = g_k + (size_t)d * LSEQ;
    for (int i = threadIdx.x; i < LSEQ; i += FFT_T) {
        bufA[i]        = make_float2(kr[i], 0.f);
        bufA[i + LSEQ] = make_float2(0.f, 0.f);
    }
    float2* out = fft8192(bufA, bufB, tw);
    const float sc = 1.0f / (float)NFFT;
    for (int i = threadIdx.x; i < NFFT; i += FFT_T)
        g_Kf[(size_t)d * NFFT + i] = make_float2(out[i].x * sc, out[i].y * sc);
}

__global__ void fftconv_kernel(const float* __restrict__ fbias)
{
    extern __shared__ float2 smem_fft[];
    float2* bufA = smem_fft;
    float2* bufB = bufA + NFFT;
    float2* tw   = bufB + NFFT;
    fft_init_tw(tw);

    const int bd = blockIdx.x;
    const int d  = bd & (DMODEL - 1);
    const float* vr = g_vg + (size_t)bd * LSEQ;

    for (int i = threadIdx.x; i < LSEQ; i += FFT_T) {
        bufA[i]        = make_float2(vr[i], 0.f);
        bufA[i + LSEQ] = make_float2(0.f, 0.f);
    }
    float2* U     = fft8192(bufA, bufB, tw);
    float2* other = (U == bufA) ? bufB : bufA;

    const float2* kf = g_Kf + (size_t)d * NFFT;
    for (int i = threadIdx.x; i < NFFT; i += FFT_T) {
        const float2 u = U[i];
        const float2 k = kf[i];
        other[i] = make_float2(u.x * k.x - u.y * k.y, -(u.x * k.y + u.y * k.x));
    }
    float2* out = fft8192(other, U, tw);

    const float fb = fbias[d];
    for (int i = threadIdx.x; i < LSEQ; i += FFT_T) {
        const size_t o = (size_t)bd * LSEQ + i;
        g_y[o] = (out[i].x + vr[i] * fb) * g_x0[o];
    }
}

// ---------------------------------------------------------------------------
// Launch
// ---------------------------------------------------------------------------
extern "C" void kernel_launch(void* const* d_in, const int* in_sizes, int n_in,
                              void* d_out, int out_size)
{
    (void)in_sizes; (void)n_in; (void)out_size;
    const float* x     = (const float*)d_in[0];
    const float* ipw   = (const float*)d_in[1];
    const float* ipb   = (const float*)d_in[2];
    const float* sw    = (const float*)d_in[3];
    const float* sb    = (const float*)d_in[4];
    const float* w0    = (const float*)d_in[5];
    const float* b0    = (const float*)d_in[6];
    const float* freq  = (const float*)d_in[7];
    const float* w1    = (const float*)d_in[8];
    const float* b1    = (const float*)d_in[9];
    const float* w2    = (const float*)d_in[10];
    const float* b2    = (const float*)d_in[11];
    const float* w3    = (const float*)d_in[12];
    const float* fbias = (const float*)d_in[13];
    const float* opw   = (const float*)d_in[14];
    const float* opb   = (const float*)d_in[15];
    float* out = (float*)d_out;

    cudaFuncSetAttribute(fftk_kernel,    cudaFuncAttributeMaxDynamicSharedMemorySize, FFT_SMEM);
    cudaFuncSetAttribute(fftconv_kernel, cudaFuncAttributeMaxDynamicSharedMemorySize, FFT_SMEM);
    cudaFuncSetAttribute(gemm_tc_kernel, cudaFuncAttributeMaxDynamicSharedMemorySize, GM_SMEM);

    __nv_bfloat16 *p_ah, *p_al, *p_w1h, *p_w1l, *p_w2h, *p_w2l;
    cudaGetSymbolAddress((void**)&p_ah,  g_ah);
    cudaGetSymbolAddress((void**)&p_al,  g_al);
    cudaGetSymbolAddress((void**)&p_w1h, g_w1h);
    cudaGetSymbolAddress((void**)&p_w1l, g_w1l);
    cudaGetSymbolAddress((void**)&p_w2h, g_w2h);
    cudaGetSymbolAddress((void**)&p_w2l, g_w2l);
    float* p_u; cudaGetSymbolAddress((void**)&p_u, g_u);

    // 0) bf16 hi/lo splits of x and weights
    {
        const int n4x = (BATCH*LSEQ*DMODEL)/4;
        split_kernel<<<(n4x+255)/256, 256>>>((const float4*)x,
            (__nv_bfloat162*)p_ah, (__nv_bfloat162*)p_al, n4x);
        const int n4w1 = (D3*DMODEL)/4;
        split_kernel<<<(n4w1+255)/256, 256>>>((const float4*)ipw,
            (__nv_bfloat162*)p_w1h, (__nv_bfloat162*)p_w1l, n4w1);
        const int n4w2 = (DMODEL*DMODEL)/4;
        split_kernel<<<(n4w2+255)/256, 256>>>((const float4*)opw,
            (__nv_bfloat162*)p_w2h, (__nv_bfloat162*)p_w2l, n4w2);
    }

    // 1) in_proj GEMM (HMMA): M=8192, N=6144, K=2048
    gemm_tc_kernel<<<dim3(D3/128, (BATCH*LSEQ)/128, 1), 256, GM_SMEM>>>(
        p_ah, p_al, p_w1h, p_w1l, ipb, p_u, D3, DMODEL, 0, 0);

    // 2) short conv + transpose + gate
    shortconv_kernel<<<dim3(LSEQ/32, DMODEL/32, BATCH), dim3(32, 8)>>>(sw, sb);

    // 3) filter MLP
    filter_h_kernel<<<LSEQ/4, dim3(ORDER, 4)>>>(w0, b0, freq, w1, b1, w2, b2);
    filter_k_kernel<<<dim3(LSEQ/32, DMODEL/32), dim3(32, 8)>>>(w3);

    // 4) FFT of filter k
    fftk_kernel<<<DMODEL, FFT_T, FFT_SMEM>>>();

    // 5) fused FFT conv + bias + output gate
    fftconv_kernel<<<BATCH*DMODEL, FFT_T, FFT_SMEM>>>(fbias);

    // 6) transpose+split y to (B, L, D) bf16
    transsplit_kernel<<<dim3(LSEQ/32, DMODEL/32, BATCH), dim3(32, 8)>>>();

    // 7) out_proj GEMM (HMMA): per batch M=4096, N=2048, K=2048
    gemm_tc_kernel<<<dim3(DMODEL/128, LSEQ/128, BATCH), 256, GM_SMEM>>>(
        p_ah, p_al, p_w2h, p_w2l, opb, out, DMODEL, DMODEL,
        (size_t)LSEQ*DMODEL, (size_t)LSEQ*DMODEL);
}

// round 4
// speedup vs baseline: 2.3511x; 1.1735x over previous
#include <cuda_runtime.h>
#include <cuda_bf16.h>
#include <math.h>
#include <stdint.h>

#define BATCH 2
#define LSEQ 4096
#define DMODEL 2048
#define D3 (3*DMODEL)
#define ORDER 64
#define NFFT 8192
#define NHALF 4096
#define FFT_T 512
#define FFT_SMEM ((NFFT + NFFT + NHALF) * (int)sizeof(float2))  // 160 KB

// ---------------------------------------------------------------------------
// Scratch (device globals; no dynamic allocation allowed)
// ---------------------------------------------------------------------------
__device__ float  g_u [(size_t)BATCH*LSEQ*D3];     // in_proj output (B, L, 3D)
__device__ float  g_x0[(size_t)BATCH*DMODEL*LSEQ]; // gate x0 (B, D, L)
__device__ float  g_vg[(size_t)BATCH*DMODEL*LSEQ]; // v * x1  (B, D, L)
__device__ float  g_y [(size_t)BATCH*DMODEL*LSEQ]; // post-conv gated (B, D, L)
__device__ float  g_h [(size_t)LSEQ*ORDER];        // filter MLP hidden (L, 64)
__device__ float  g_k [(size_t)DMODEL*LSEQ];       // filter kernel (D, L)
__device__ float2 g_Kf[(size_t)DMODEL*NFFT];       // FFT(k)/NFFT per channel

// bf16 split buffers (hi/lo error compensation)
__device__ __nv_bfloat16 g_ah [(size_t)BATCH*LSEQ*DMODEL];
__device__ __nv_bfloat16 g_al [(size_t)BATCH*LSEQ*DMODEL];
__device__ __nv_bfloat16 g_w1h[(size_t)D3*DMODEL];
__device__ __nv_bfloat16 g_w1l[(size_t)D3*DMODEL];
__device__ __nv_bfloat16 g_w2h[(size_t)DMODEL*DMODEL];
__device__ __nv_bfloat16 g_w2l[(size_t)DMODEL*DMODEL];

// ---------------------------------------------------------------------------
// Warp-MMA GEMM (same as R3): mma.sync m16n8k16 bf16 hi/lo compensated
// ---------------------------------------------------------------------------
#define GK_CHUNK 32
#define ROWPAD 40
#define ST_ELEMS (128*ROWPAD)
#define STAGE_ELEMS (4*ST_ELEMS)
#define NSTAGE 4
#define GM_SMEM (NSTAGE*STAGE_ELEMS*2)

__device__ __forceinline__ void cpa16(uint32_t s, const void* g) {
    asm volatile("cp.async.cg.shared.global [%0], [%1], 16;" :: "r"(s), "l"(g));
}
#define CP_COMMIT() asm volatile("cp.async.commit_group;" ::: "memory")
#define CP_WAIT2()  asm volatile("cp.async.wait_group 2;" ::: "memory")

#define LDSM_X4(r, addr) \
    asm volatile("ldmatrix.sync.aligned.m8n8.x4.shared.b16 {%0,%1,%2,%3}, [%4];" \
        : "=r"((r)[0]), "=r"((r)[1]), "=r"((r)[2]), "=r"((r)[3]) : "r"(addr))

#define MMA16816(c, a, b) \
    asm volatile("mma.sync.aligned.m16n8k16.row.col.f32.bf16.bf16.f32 " \
        "{%0,%1,%2,%3}, {%4,%5,%6,%7}, {%8,%9}, {%0,%1,%2,%3};" \
        : "+f"((c)[0]), "+f"((c)[1]), "+f"((c)[2]), "+f"((c)[3]) \
        : "r"((a)[0]), "r"((a)[1]), "r"((a)[2]), "r"((a)[3]), \
          "r"((b)[0]), "r"((b)[1]))

__global__ void __launch_bounds__(256)
gemm_tc_kernel(const __nv_bfloat16* __restrict__ Ah, const __nv_bfloat16* __restrict__ Al,
               const __nv_bfloat16* __restrict__ Wh, const __nv_bfloat16* __restrict__ Wl,
               const float* __restrict__ bias, float* __restrict__ C,
               int Ntot, int K, size_t strideA, size_t strideC)
{
    extern __shared__ char smem[];
    const uint32_t sbase = (uint32_t)__cvta_generic_to_shared(smem);
    const int tid  = threadIdx.x;
    const int lane = tid & 31;
    const int wid  = tid >> 5;
    const int wm   = wid & 3;
    const int wn   = wid >> 2;

    const int z = blockIdx.z;
    const __nv_bfloat16* Ahb = Ah + (size_t)z * strideA;
    const __nv_bfloat16* Alb = Al + (size_t)z * strideA;
    float* Cb = C + (size_t)z * strideC;

    const int col0 = blockIdx.x * 128;
    const int row0 = blockIdx.y * 128;
    const int nchunk = K / GK_CHUNK;

    float acc[2][8][4];
#pragma unroll
    for (int i = 0; i < 2; i++)
#pragma unroll
        for (int j = 0; j < 8; j++)
#pragma unroll
            for (int q = 0; q < 4; q++) acc[i][j][q] = 0.f;

    auto load_stage = [&](int stage, int k0) {
        const uint32_t sb = sbase + (uint32_t)(stage * STAGE_ELEMS) * 2;
#pragma unroll
        for (int i = 0; i < 2; i++) {
            const int seg = tid + i * 256;
            const int r = seg >> 2, cs = seg & 3;
            const size_t ga = (size_t)(row0 + r) * K + k0 + cs * 8;
            const size_t gb = (size_t)(col0 + r) * K + k0 + cs * 8;
            const uint32_t so = (uint32_t)(r * ROWPAD + cs * 8) * 2;
            cpa16(sb + so,                Ahb + ga);
            cpa16(sb + so + ST_ELEMS*2,   Alb + ga);
            cpa16(sb + so + 2*ST_ELEMS*2, Wh  + gb);
            cpa16(sb + so + 3*ST_ELEMS*2, Wl  + gb);
        }
    };

    for (int s = 0; s < 3; s++) { load_stage(s, s * GK_CHUNK); CP_COMMIT(); }

    const int a_row = (lane & 15);
    const int a_col = (lane >> 4) << 3;
    const int b_row2 = (((lane >> 3) & 3) >> 1) * 8 + (lane & 7);
    const int b_col = ((lane >> 3) & 1) << 3;

    for (int c = 0; c < nchunk; c++) {
        CP_WAIT2();
        __syncthreads();
        if (c + 3 < nchunk) load_stage((c + 3) & (NSTAGE - 1), (c + 3) * GK_CHUNK);
        CP_COMMIT();

        const uint32_t stb = sbase + (uint32_t)((c & (NSTAGE - 1)) * STAGE_ELEMS) * 2;
#pragma unroll
        for (int step = 0; step < 2; step++) {
            const int kl = step * 16;
            uint32_t ah[2][4], al[2][4];
#pragma unroll
            for (int mt = 0; mt < 2; mt++) {
                const uint32_t off = (uint32_t)((wm*32 + mt*16 + a_row) * ROWPAD + kl + a_col) * 2;
                LDSM_X4(ah[mt], stb + off);
                LDSM_X4(al[mt], stb + ST_ELEMS*2 + off);
            }
            uint32_t bh[8][2], bl[8][2];
#pragma unroll
            for (int p = 0; p < 4; p++) {
                const uint32_t off = (uint32_t)((wn*64 + p*16 + b_row2) * ROWPAD + kl + b_col) * 2;
                uint32_t t[4];
                LDSM_X4(t, stb + 2*ST_ELEMS*2 + off);
                bh[p*2][0]=t[0]; bh[p*2][1]=t[1]; bh[p*2+1][0]=t[2]; bh[p*2+1][1]=t[3];
                LDSM_X4(t, stb + 3*ST_ELEMS*2 + off);
                bl[p*2][0]=t[0]; bl[p*2][1]=t[1]; bl[p*2+1][0]=t[2]; bl[p*2+1][1]=t[3];
            }
#pragma unroll
            for (int mt = 0; mt < 2; mt++)
#pragma unroll
                for (int nt = 0; nt < 8; nt++) {
                    MMA16816(acc[mt][nt], ah[mt], bh[nt]);
                    MMA16816(acc[mt][nt], ah[mt], bl[nt]);
                    MMA16816(acc[mt][nt], al[mt], bh[nt]);
                }
        }
    }

#pragma unroll
    for (int mt = 0; mt < 2; mt++) {
        const int r0g = row0 + wm*32 + mt*16 + (lane >> 2);
#pragma unroll
        for (int nt = 0; nt < 8; nt++) {
            const int col = col0 + wn*64 + nt*8 + (lane & 3)*2;
            const float b0 = bias[col], b1 = bias[col+1];
            float2 v0 = make_float2(acc[mt][nt][0] + b0, acc[mt][nt][1] + b1);
            float2 v1 = make_float2(acc[mt][nt][2] + b0, acc[mt][nt][3] + b1);
            *(float2*)(Cb + (size_t)r0g       * Ntot + col) = v0;
            *(float2*)(Cb + (size_t)(r0g + 8) * Ntot + col) = v1;
        }
    }
}

// ---------------------------------------------------------------------------
// fp32 -> bf16 hi/lo split
// ---------------------------------------------------------------------------
__global__ void __launch_bounds__(256)
split_kernel(const float4* __restrict__ src, __nv_bfloat162* __restrict__ hi,
             __nv_bfloat162* __restrict__ lo, int n4)
{
    const int i = blockIdx.x * 256 + threadIdx.x;
    if (i >= n4) return;
    const float4 v = src[i];
    __nv_bfloat162 h0 = __floats2bfloat162_rn(v.x, v.y);
    __nv_bfloat162 h1 = __floats2bfloat162_rn(v.z, v.w);
    float2 f0 = __bfloat1622float2(h0);
    float2 f1 = __bfloat1622float2(h1);
    hi[i*2+0] = h0;
    hi[i*2+1] = h1;
    lo[i*2+0] = __floats2bfloat162_rn(v.x - f0.x, v.y - f0.y);
    lo[i*2+1] = __floats2bfloat162_rn(v.z - f1.x, v.w - f1.y);
}

__global__ void __launch_bounds__(256)
transsplit_kernel()
{
    __shared__ float t[32][33];
    const int b = blockIdx.z, d0 = blockIdx.y * 32, l0 = blockIdx.x * 32;
    const int tx = threadIdx.x, ty = threadIdx.y;
    for (int dy = ty; dy < 32; dy += 8)
        t[dy][tx] = g_y[((size_t)b * DMODEL + d0 + dy) * LSEQ + l0 + tx];
    __syncthreads();
    for (int ly = ty; ly < 32; ly += 8) {
        const float v = t[tx][ly];
        const size_t o = ((size_t)b * LSEQ + l0 + ly) * DMODEL + d0 + tx;
        const __nv_bfloat16 h = __float2bfloat16(v);
        g_ah[o] = h;
        g_al[o] = __float2bfloat16(v - __bfloat162float(h));
    }
}

// ---------------------------------------------------------------------------
// Short conv + transpose + gate
// ---------------------------------------------------------------------------
__global__ void __launch_bounds__(256)
shortconv_kernel(const float* __restrict__ sw, const float* __restrict__ sb)
{
    __shared__ float su[3][34][33];
    const int b = blockIdx.z, l0 = blockIdx.x * 32, d0 = blockIdx.y * 32;
    const int tx = threadIdx.x, ty = threadIdx.y;

#pragma unroll
    for (int g = 0; g < 3; g++)
        for (int li = ty; li < 34; li += 8) {
            const int l = l0 + li - 2;
            su[g][li][tx] = (l >= 0)
                ? g_u[((size_t)b * LSEQ + l) * D3 + g * DMODEL + d0 + tx] : 0.f;
        }
    __syncthreads();

    const int l = l0 + tx;
    for (int di = ty; di < 32; di += 8) {
        const int d = d0 + di;
        float r[3];
#pragma unroll
        for (int g = 0; g < 3; g++) {
            const int c = g * DMODEL + d;
            r[g] = sw[c*3+0] * su[g][tx][di]
                 + sw[c*3+1] * su[g][tx+1][di]
                 + sw[c*3+2] * su[g][tx+2][di]
                 + sb[c];
        }
        const size_t o = ((size_t)b * DMODEL + d) * LSEQ + l;
        g_x0[o] = r[0];
        g_vg[o] = r[1] * r[2];
    }
}

// ---------------------------------------------------------------------------
// Filter MLP hidden state h (L, 64)
// ---------------------------------------------------------------------------
__global__ void __launch_bounds__(256)
filter_h_kernel(const float* __restrict__ w0, const float* __restrict__ b0,
                const float* __restrict__ freq,
                const float* __restrict__ w1, const float* __restrict__ b1,
                const float* __restrict__ w2, const float* __restrict__ b2)
{
    __shared__ float ws[ORDER][ORDER + 1];
    __shared__ float h1[4][ORDER + 1];
    const int o  = threadIdx.x;
    const int lq = threadIdx.y;
    const int l  = blockIdx.x * 4 + lq;
    const int tid = lq * ORDER + o;

    const float t   = (float)l / (float)(LSEQ - 1);
    const float wl  = 2.f * 3.14159265358979323846f * (float)l / (float)LSEQ;
    const float ang = 1e-4f * wl;
    const float z1 = cosf(ang), z2 = -sinf(ang);
    const float fr = freq[o];
    float v = t * w0[o*3+0] + z1 * w0[o*3+1] + z2 * w0[o*3+2] + b0[o];
    h1[lq][o] = sinf(fr * v);
    for (int i = tid; i < ORDER * ORDER; i += 256) ws[i >> 6][i & 63] = w1[i];
    __syncthreads();

    float s = b1[o];
#pragma unroll 8
    for (int j = 0; j < ORDER; j++) s = fmaf(ws[o][j], h1[lq][j], s);
    const float h2v = sinf(fr * s);
    __syncthreads();

    h1[lq][o] = h2v;
    for (int i = tid; i < ORDER * ORDER; i += 256) ws[i >> 6][i & 63] = w2[i];
    __syncthreads();

    s = b2[o];
#pragma unroll 8
    for (int j = 0; j < ORDER; j++) s = fmaf(ws[o][j], h1[lq][j], s);
    g_h[(size_t)l * ORDER + o] = sinf(fr * s);
}

__global__ void __launch_bounds__(256)
filter_k_kernel(const float* __restrict__ w3)
{
    __shared__ float hs[32][ORDER + 1];
    const int l0 = blockIdx.x * 32, d0 = blockIdx.y * 32;
    const int tx = threadIdx.x, ty = threadIdx.y;

    for (int i = ty; i < 32; i += 8) {
        hs[i][tx]      = g_h[(size_t)(l0 + i) * ORDER + tx];
        hs[i][tx + 32] = g_h[(size_t)(l0 + i) * ORDER + tx + 32];
    }
    __syncthreads();

    const int l = l0 + tx;
    const float t = (float)l / (float)(LSEQ - 1);
    const float min_decay = -4.60517018598809136804f / 1.5f;
    const float max_decay = -4.60517018598809136804f / 0.3f;
    for (int di = ty; di < 32; di += 8) {
        const int d = d0 + di;
        float s = 0.f;
#pragma unroll 8
        for (int j = 0; j < ORDER; j++)
            s = fmaf(w3[(size_t)d * ORDER + j], hs[tx][j], s);
        const float delta = min_decay + (max_decay - min_decay) * (float)d / (float)(DMODEL - 1);
        g_k[(size_t)d * LSEQ + l] = s * expf(-t * fabsf(delta));
    }
}

// ---------------------------------------------------------------------------
// Mixed-radix Stockham FFT, N=8192: 6 radix-4 stages + 1 radix-2 stage
// tw[t] = exp(-2*pi*i*t/8192), t in [0, 4096)
// ---------------------------------------------------------------------------
__device__ __forceinline__ void fft_init_tw(float2* tw)
{
    for (int i = threadIdx.x; i < NHALF; i += FFT_T) {
        float s, c;
        sincosf(-3.14159265358979323846f * (float)i / (float)NHALF, &s, &c);
        tw[i] = make_float2(c, s);
    }
}

__device__ __forceinline__ float2 cmul(float2 a, float2 b) {
    return make_float2(a.x*b.x - a.y*b.y, a.x*b.y + a.y*b.x);
}

__device__ __forceinline__ float2* fft8192(float2* srcBuf, float2* dstBuf, const float2* tw)
{
    float2* src = srcBuf;
    float2* dst = dstBuf;
    int m = 1;
#pragma unroll 1
    for (int s = 0; s < 6; s++) {
        __syncthreads();
#pragma unroll 1
        for (int i = threadIdx.x; i < 2048; i += FFT_T) {
            const int k  = i & (m - 1);
            const int jm = i - k;
            const float2 x0 = src[i];
            const float2 x1 = src[i + 2048];
            const float2 x2 = src[i + 4096];
            const float2 x3 = src[i + 6144];
            const float2 a = make_float2(x0.x + x2.x, x0.y + x2.y);
            const float2 b = make_float2(x0.x - x2.x, x0.y - x2.y);
            const float2 c = make_float2(x1.x + x3.x, x1.y + x3.y);
            const float2 d = make_float2(x1.x - x3.x, x1.y - x3.y);
            const float2 y0 = make_float2(a.x + c.x, a.y + c.y);
            const float2 y2 = make_float2(a.x - c.x, a.y - c.y);
            const float2 y1 = make_float2(b.x + d.y, b.y - d.x);   // b - i*d
            const float2 y3 = make_float2(b.x - d.y, b.y + d.x);   // b + i*d
            const float2 w1 = tw[jm];
            const float2 w2 = tw[2 * jm];
            const float2 w3 = cmul(w1, w2);
            const int o = 4 * jm + k;
            dst[o]         = y0;
            dst[o + m]     = cmul(y1, w1);
            dst[o + 2*m]   = cmul(y2, w2);
            dst[o + 3*m]   = cmul(y3, w3);
        }
        float2* t = src; src = dst; dst = t;
        m <<= 2;
    }
    // final radix-2 stage, m=4096 (twiddle-free: j==0)
    __syncthreads();
#pragma unroll 1
    for (int i = threadIdx.x; i < 4096; i += FFT_T) {
        const float2 x0 = src[i];
        const float2 x1 = src[i + 4096];
        dst[i]        = make_float2(x0.x + x1.x, x0.y + x1.y);
        dst[i + 4096] = make_float2(x0.x - x1.x, x0.y - x1.y);
    }
    float2* t = src; src = dst; dst = t;
    __syncthreads();
    return src;
}

// FFT of filter k, two channels packed per block (real + imag)
__global__ void fftk_kernel()
{
    extern __shared__ float2 smem_fft[];
    float2* bufA = smem_fft;
    float2* bufB = bufA + NFFT;
    float2* tw   = bufB + NFFT;
    fft_init_tw(tw);

    const int d0 = blockIdx.x * 2;
    const float* k0 = g_k + (size_t)d0 * LSEQ;
    const float* k1 = k0 + LSEQ;
    for (int i = threadIdx.x; i < LSEQ; i += FFT_T) {
        bufA[i]        = make_float2(k0[i], k1[i]);
        bufA[i + LSEQ] = make_float2(0.f, 0.f);
    }
    float2* Z = fft8192(bufA, bufB, tw);

    const float hc = 0.5f / (float)NFFT;
    float2* o0 = g_Kf + (size_t)d0 * NFFT;
    float2* o1 = o0 + NFFT;
    for (int i = threadIdx.x; i < NFFT; i += FFT_T) {
        const int ir = (NFFT - i) & (NFFT - 1);
        const float2 A = Z[i];
        const float2 Zr = Z[ir];
        // B = conj(Z[ir])
        const float sx = A.x + Zr.x, sy = A.y - Zr.y;   // A + B
        const float px = A.x - Zr.x, py = A.y + Zr.y;   // A - B
        o0[i] = make_float2(sx * hc, sy * hc);
        o1[i] = make_float2(py * hc, -px * hc);         // -i*(A-B)/2 * (1/N)
    }
}

// Fused FFT conv: both batches of one channel packed per block.
__global__ void fftconv_kernel(const float* __restrict__ fbias)
{
    extern __shared__ float2 smem_fft[];
    float2* bufA = smem_fft;
    float2* bufB = bufA + NFFT;
    float2* tw   = bufB + NFFT;
    fft_init_tw(tw);

    const int d = blockIdx.x;
    const float* v0 = g_vg + (size_t)d * LSEQ;                    // batch 0
    const float* v1 = g_vg + ((size_t)DMODEL + d) * LSEQ;         // batch 1

    for (int i = threadIdx.x; i < LSEQ; i += FFT_T) {
        bufA[i]        = make_float2(v0[i], v1[i]);
        bufA[i + LSEQ] = make_float2(0.f, 0.f);
    }
    float2* Z     = fft8192(bufA, bufB, tw);
    float2* other = (Z == bufA) ? bufB : bufA;

    const float2* kf = g_Kf + (size_t)d * NFFT;
    for (int i = threadIdx.x; i < NFFT; i += FFT_T) {
        const int ir = (NFFT - i) & (NFFT - 1);
        const float2 A = Z[i];
        const float2 Zr = Z[ir];
        // U0 = (A + conj(Zr))/2 ; U1 = -i*(A - conj(Zr))/2
        const float u0x = 0.5f * (A.x + Zr.x), u0y = 0.5f * (A.y - Zr.y);
        const float px  = 0.5f * (A.x - Zr.x), py  = 0.5f * (A.y + Zr.y);
        const float u1x = py, u1y = -px;
        const float2 k = kf[i];
        // Y0 = U0*k ; Y1 = U1*k ; S = Y0 + i*Y1 ; store conj(S)
        const float y0x = u0x * k.x - u0y * k.y;
        const float y0y = u0x * k.y + u0y * k.x;
        const float y1x = u1x * k.x - u1y * k.y;
        const float y1y = u1x * k.y + u1y * k.x;
        other[i] = make_float2(y0x - y1y, -(y0y + y1x));
    }
    float2* out = fft8192(other, Z, tw);

    const float fb = fbias[d];
    for (int i = threadIdx.x; i < LSEQ; i += FFT_T) {
        const size_t o0 = (size_t)d * LSEQ + i;
        const size_t o1 = ((size_t)DMODEL + d) * LSEQ + i;
        g_y[o0] = (out[i].x + v0[i] * fb) * g_x0[o0];
        g_y[o1] = (-out[i].y + v1[i] * fb) * g_x0[o1];
    }
}

// ---------------------------------------------------------------------------
// Launch
// ---------------------------------------------------------------------------
extern "C" void kernel_launch(void* const* d_in, const int* in_sizes, int n_in,
                              void* d_out, int out_size)
{
    (void)in_sizes; (void)n_in; (void)out_size;
    const float* x     = (const float*)d_in[0];
    const float* ipw   = (const float*)d_in[1];
    const float* ipb   = (const float*)d_in[2];
    const float* sw    = (const float*)d_in[3];
    const float* sb    = (const float*)d_in[4];
    const float* w0    = (const float*)d_in[5];
    const float* b0    = (const float*)d_in[6];
    const float* freq  = (const float*)d_in[7];
    const float* w1    = (const float*)d_in[8];
    const float* b1    = (const float*)d_in[9];
    const float* w2    = (const float*)d_in[10];
    const float* b2    = (const float*)d_in[11];
    const float* w3    = (const float*)d_in[12];
    const float* fbias = (const float*)d_in[13];
    const float* opw   = (const float*)d_in[14];
    const float* opb   = (const float*)d_in[15];
    float* out = (float*)d_out;

    cudaFuncSetAttribute(fftk_kernel,    cudaFuncAttributeMaxDynamicSharedMemorySize, FFT_SMEM);
    cudaFuncSetAttribute(fftconv_kernel, cudaFuncAttributeMaxDynamicSharedMemorySize, FFT_SMEM);
    cudaFuncSetAttribute(gemm_tc_kernel, cudaFuncAttributeMaxDynamicSharedMemorySize, GM_SMEM);

    __nv_bfloat16 *p_ah, *p_al, *p_w1h, *p_w1l, *p_w2h, *p_w2l;
    cudaGetSymbolAddress((void**)&p_ah,  g_ah);
    cudaGetSymbolAddress((void**)&p_al,  g_al);
    cudaGetSymbolAddress((void**)&p_w1h, g_w1h);
    cudaGetSymbolAddress((void**)&p_w1l, g_w1l);
    cudaGetSymbolAddress((void**)&p_w2h, g_w2h);
    cudaGetSymbolAddress((void**)&p_w2l, g_w2l);
    float* p_u; cudaGetSymbolAddress((void**)&p_u, g_u);

    // 0) bf16 hi/lo splits of x and weights
    {
        const int n4x = (BATCH*LSEQ*DMODEL)/4;
        split_kernel<<<(n4x+255)/256, 256>>>((const float4*)x,
            (__nv_bfloat162*)p_ah, (__nv_bfloat162*)p_al, n4x);
        const int n4w1 = (D3*DMODEL)/4;
        split_kernel<<<(n4w1+255)/256, 256>>>((const float4*)ipw,
            (__nv_bfloat162*)p_w1h, (__nv_bfloat162*)p_w1l, n4w1);
        const int n4w2 = (DMODEL*DMODEL)/4;
        split_kernel<<<(n4w2+255)/256, 256>>>((const float4*)opw,
            (__nv_bfloat162*)p_w2h, (__nv_bfloat162*)p_w2l, n4w2);
    }

    // 1) in_proj GEMM (HMMA): M=8192, N=6144, K=2048
    gemm_tc_kernel<<<dim3(D3/128, (BATCH*LSEQ)/128, 1), 256, GM_SMEM>>>(
        p_ah, p_al, p_w1h, p_w1l, ipb, p_u, D3, DMODEL, 0, 0);

    // 2) short conv + transpose + gate
    shortconv_kernel<<<dim3(LSEQ/32, DMODEL/32, BATCH), dim3(32, 8)>>>(sw, sb);

    // 3) filter MLP
    filter_h_kernel<<<LSEQ/4, dim3(ORDER, 4)>>>(w0, b0, freq, w1, b1, w2, b2);
    filter_k_kernel<<<dim3(LSEQ/32, DMODEL/32), dim3(32, 8)>>>(w3);

    // 4) FFT of filter k (two channels per block)
    fftk_kernel<<<DMODEL/2, FFT_T, FFT_SMEM>>>();

    // 5) fused FFT conv + bias + output gate (both batches per block)
    fftconv_kernel<<<DMODEL, FFT_T, FFT_SMEM>>>(fbias);

    // 6) transpose+split y to (B, L, D) bf16
    transsplit_kernel<<<dim3(LSEQ/32, DMODEL/32, BATCH), dim3(32, 8)>>>();

    // 7) out_proj GEMM (HMMA): per batch M=4096, N=2048, K=2048
    gemm_tc_kernel<<<dim3(DMODEL/128, LSEQ/128, BATCH), 256, GM_SMEM>>>(
        p_ah, p_al, p_w2h, p_w2l, opb, out, DMODEL, DMODEL,
        (size_t)LSEQ*DMODEL, (size_t)LSEQ*DMODEL);
}

// round 5
// speedup vs baseline: 2.7474x; 1.1686x over previous
#include <cuda_runtime.h>
#include <cuda_bf16.h>
#include <math.h>
#include <stdint.h>

#define BATCH 2
#define LSEQ 4096
#define DMODEL 2048
#define D3 (3*DMODEL)
#define ORDER 64
#define NFFT 8192
#define NHALF 4096
#define FFT_T 512
#define FFT_SMEM ((2*NFFT + 512) * (int)sizeof(float2))   // 135168 B

// ---------------------------------------------------------------------------
// Scratch (device globals)
// ---------------------------------------------------------------------------
__device__ float  g_u [(size_t)BATCH*LSEQ*D3];
__device__ float  g_x0[(size_t)BATCH*DMODEL*LSEQ];
__device__ float  g_vg[(size_t)BATCH*DMODEL*LSEQ];
__device__ float  g_y [(size_t)BATCH*DMODEL*LSEQ];
__device__ float  g_h [(size_t)LSEQ*ORDER];
__device__ float  g_k [(size_t)DMODEL*LSEQ];
__device__ float2 g_Kf[(size_t)DMODEL*NFFT];

__device__ __nv_bfloat16 g_ah [(size_t)BATCH*LSEQ*DMODEL];
__device__ __nv_bfloat16 g_al [(size_t)BATCH*LSEQ*DMODEL];
__device__ __nv_bfloat16 g_w1h[(size_t)D3*DMODEL];
__device__ __nv_bfloat16 g_w1l[(size_t)D3*DMODEL];
__device__ __nv_bfloat16 g_w2h[(size_t)DMODEL*DMODEL];
__device__ __nv_bfloat16 g_w2l[(size_t)DMODEL*DMODEL];

// ---------------------------------------------------------------------------
// Warp-MMA GEMM: 2-stage cp.async, 2 CTAs/SM
// ---------------------------------------------------------------------------
#define GK_CHUNK 32
#define ROWPAD 40
#define ST_ELEMS (128*ROWPAD)
#define STAGE_ELEMS (4*ST_ELEMS)
#define NSTAGE 2
#define GM_SMEM (NSTAGE*STAGE_ELEMS*2)    // 81920 B

__device__ __forceinline__ void cpa16(uint32_t s, const void* g) {
    asm volatile("cp.async.cg.shared.global [%0], [%1], 16;" :: "r"(s), "l"(g));
}
#define CP_COMMIT() asm volatile("cp.async.commit_group;" ::: "memory")
#define CP_WAIT1()  asm volatile("cp.async.wait_group 1;" ::: "memory")

#define LDSM_X4(r, addr) \
    asm volatile("ldmatrix.sync.aligned.m8n8.x4.shared.b16 {%0,%1,%2,%3}, [%4];" \
        : "=r"((r)[0]), "=r"((r)[1]), "=r"((r)[2]), "=r"((r)[3]) : "r"(addr))

#define MMA16816(c, a, b) \
    asm volatile("mma.sync.aligned.m16n8k16.row.col.f32.bf16.bf16.f32 " \
        "{%0,%1,%2,%3}, {%4,%5,%6,%7}, {%8,%9}, {%0,%1,%2,%3};" \
        : "+f"((c)[0]), "+f"((c)[1]), "+f"((c)[2]), "+f"((c)[3]) \
        : "r"((a)[0]), "r"((a)[1]), "r"((a)[2]), "r"((a)[3]), \
          "r"((b)[0]), "r"((b)[1]))

__global__ void __launch_bounds__(256, 2)
gemm_tc_kernel(const __nv_bfloat16* __restrict__ Ah, const __nv_bfloat16* __restrict__ Al,
               const __nv_bfloat16* __restrict__ Wh, const __nv_bfloat16* __restrict__ Wl,
               const float* __restrict__ bias, float* __restrict__ C,
               int Ntot, int K, size_t strideA, size_t strideC)
{
    extern __shared__ char smem[];
    const uint32_t sbase = (uint32_t)__cvta_generic_to_shared(smem);
    const int tid  = threadIdx.x;
    const int lane = tid & 31;
    const int wid  = tid >> 5;
    const int wm   = wid & 3;
    const int wn   = wid >> 2;

    const int z = blockIdx.z;
    const __nv_bfloat16* Ahb = Ah + (size_t)z * strideA;
    const __nv_bfloat16* Alb = Al + (size_t)z * strideA;
    float* Cb = C + (size_t)z * strideC;

    const int col0 = blockIdx.x * 128;
    const int row0 = blockIdx.y * 128;
    const int nchunk = K / GK_CHUNK;

    float acc[2][8][4];
#pragma unroll
    for (int i = 0; i < 2; i++)
#pragma unroll
        for (int j = 0; j < 8; j++)
#pragma unroll
            for (int q = 0; q < 4; q++) acc[i][j][q] = 0.f;

    auto load_stage = [&](int stage, int k0) {
        const uint32_t sb = sbase + (uint32_t)(stage * STAGE_ELEMS) * 2;
#pragma unroll
        for (int i = 0; i < 2; i++) {
            const int seg = tid + i * 256;
            const int r = seg >> 2, cs = seg & 3;
            const size_t ga = (size_t)(row0 + r) * K + k0 + cs * 8;
            const size_t gb = (size_t)(col0 + r) * K + k0 + cs * 8;
            const uint32_t so = (uint32_t)(r * ROWPAD + cs * 8) * 2;
            cpa16(sb + so,                Ahb + ga);
            cpa16(sb + so + ST_ELEMS*2,   Alb + ga);
            cpa16(sb + so + 2*ST_ELEMS*2, Wh  + gb);
            cpa16(sb + so + 3*ST_ELEMS*2, Wl  + gb);
        }
    };

    load_stage(0, 0);        CP_COMMIT();
    load_stage(1, GK_CHUNK); CP_COMMIT();

    const int a_row = (lane & 15);
    const int a_col = (lane >> 4) << 3;
    const int b_row2 = (((lane >> 3) & 3) >> 1) * 8 + (lane & 7);
    const int b_col = ((lane >> 3) & 1) << 3;

    for (int c = 0; c < nchunk; c++) {
        CP_WAIT1();
        __syncthreads();

        const uint32_t stb = sbase + (uint32_t)((c & 1) * STAGE_ELEMS) * 2;
#pragma unroll
        for (int step = 0; step < 2; step++) {
            const int kl = step * 16;
            uint32_t ah[2][4], al[2][4];
#pragma unroll
            for (int mt = 0; mt < 2; mt++) {
                const uint32_t off = (uint32_t)((wm*32 + mt*16 + a_row) * ROWPAD + kl + a_col) * 2;
                LDSM_X4(ah[mt], stb + off);
                LDSM_X4(al[mt], stb + ST_ELEMS*2 + off);
            }
            uint32_t bh[8][2], bl[8][2];
#pragma unroll
            for (int p = 0; p < 4; p++) {
                const uint32_t off = (uint32_t)((wn*64 + p*16 + b_row2) * ROWPAD + kl + b_col) * 2;
                uint32_t t[4];
                LDSM_X4(t, stb + 2*ST_ELEMS*2 + off);
                bh[p*2][0]=t[0]; bh[p*2][1]=t[1]; bh[p*2+1][0]=t[2]; bh[p*2+1][1]=t[3];
                LDSM_X4(t, stb + 3*ST_ELEMS*2 + off);
                bl[p*2][0]=t[0]; bl[p*2][1]=t[1]; bl[p*2+1][0]=t[2]; bl[p*2+1][1]=t[3];
            }
#pragma unroll
            for (int mt = 0; mt < 2; mt++)
#pragma unroll
                for (int nt = 0; nt < 8; nt++) {
                    MMA16816(acc[mt][nt], ah[mt], bh[nt]);
                    MMA16816(acc[mt][nt], ah[mt], bl[nt]);
                    MMA16816(acc[mt][nt], al[mt], bh[nt]);
                }
        }
        __syncthreads();
        if (c + 2 < nchunk) { load_stage(c & 1, (c + 2) * GK_CHUNK); CP_COMMIT(); }
    }

#pragma unroll
    for (int mt = 0; mt < 2; mt++) {
        const int r0g = row0 + wm*32 + mt*16 + (lane >> 2);
#pragma unroll
        for (int nt = 0; nt < 8; nt++) {
            const int col = col0 + wn*64 + nt*8 + (lane & 3)*2;
            const float b0 = bias[col], b1 = bias[col+1];
            float2 v0 = make_float2(acc[mt][nt][0] + b0, acc[mt][nt][1] + b1);
            float2 v1 = make_float2(acc[mt][nt][2] + b0, acc[mt][nt][3] + b1);
            *(float2*)(Cb + (size_t)r0g       * Ntot + col) = v0;
            *(float2*)(Cb + (size_t)(r0g + 8) * Ntot + col) = v1;
        }
    }
}

// ---------------------------------------------------------------------------
// fp32 -> bf16 hi/lo split
// ---------------------------------------------------------------------------
__global__ void __launch_bounds__(256)
split_kernel(const float4* __restrict__ src, __nv_bfloat162* __restrict__ hi,
             __nv_bfloat162* __restrict__ lo, int n4)
{
    const int i = blockIdx.x * 256 + threadIdx.x;
    if (i >= n4) return;
    const float4 v = src[i];
    __nv_bfloat162 h0 = __floats2bfloat162_rn(v.x, v.y);
    __nv_bfloat162 h1 = __floats2bfloat162_rn(v.z, v.w);
    float2 f0 = __bfloat1622float2(h0);
    float2 f1 = __bfloat1622float2(h1);
    hi[i*2+0] = h0;
    hi[i*2+1] = h1;
    lo[i*2+0] = __floats2bfloat162_rn(v.x - f0.x, v.y - f0.y);
    lo[i*2+1] = __floats2bfloat162_rn(v.z - f1.x, v.w - f1.y);
}

__global__ void __launch_bounds__(256)
transsplit_kernel()
{
    __shared__ float t[32][33];
    const int b = blockIdx.z, d0 = blockIdx.y * 32, l0 = blockIdx.x * 32;
    const int tx = threadIdx.x, ty = threadIdx.y;
    for (int dy = ty; dy < 32; dy += 8)
        t[dy][tx] = g_y[((size_t)b * DMODEL + d0 + dy) * LSEQ + l0 + tx];
    __syncthreads();
    for (int ly = ty; ly < 32; ly += 8) {
        const float v = t[tx][ly];
        const size_t o = ((size_t)b * LSEQ + l0 + ly) * DMODEL + d0 + tx;
        const __nv_bfloat16 h = __float2bfloat16(v);
        g_ah[o] = h;
        g_al[o] = __float2bfloat16(v - __bfloat162float(h));
    }
}

// ---------------------------------------------------------------------------
// Short conv + transpose + gate
// ---------------------------------------------------------------------------
__global__ void __launch_bounds__(256)
shortconv_kernel(const float* __restrict__ sw, const float* __restrict__ sb)
{
    __shared__ float su[3][34][33];
    const int b = blockIdx.z, l0 = blockIdx.x * 32, d0 = blockIdx.y * 32;
    const int tx = threadIdx.x, ty = threadIdx.y;

#pragma unroll
    for (int g = 0; g < 3; g++)
        for (int li = ty; li < 34; li += 8) {
            const int l = l0 + li - 2;
            su[g][li][tx] = (l >= 0)
                ? g_u[((size_t)b * LSEQ + l) * D3 + g * DMODEL + d0 + tx] : 0.f;
        }
    __syncthreads();

    const int l = l0 + tx;
    for (int di = ty; di < 32; di += 8) {
        const int d = d0 + di;
        float r[3];
#pragma unroll
        for (int g = 0; g < 3; g++) {
            const int c = g * DMODEL + d;
            r[g] = sw[c*3+0] * su[g][tx][di]
                 + sw[c*3+1] * su[g][tx+1][di]
                 + sw[c*3+2] * su[g][tx+2][di]
                 + sb[c];
        }
        const size_t o = ((size_t)b * DMODEL + d) * LSEQ + l;
        g_x0[o] = r[0];
        g_vg[o] = r[1] * r[2];
    }
}

// ---------------------------------------------------------------------------
// Filter MLP
// ---------------------------------------------------------------------------
__global__ void __launch_bounds__(256)
filter_h_kernel(const float* __restrict__ w0, const float* __restrict__ b0,
                const float* __restrict__ freq,
                const float* __restrict__ w1, const float* __restrict__ b1,
                const float* __restrict__ w2, const float* __restrict__ b2)
{
    __shared__ float ws[ORDER][ORDER + 1];
    __shared__ float h1[4][ORDER + 1];
    const int o  = threadIdx.x;
    const int lq = threadIdx.y;
    const int l  = blockIdx.x * 4 + lq;
    const int tid = lq * ORDER + o;

    const float t   = (float)l / (float)(LSEQ - 1);
    const float wl  = 2.f * 3.14159265358979323846f * (float)l / (float)LSEQ;
    const float ang = 1e-4f * wl;
    const float z1 = cosf(ang), z2 = -sinf(ang);
    const float fr = freq[o];
    float v = t * w0[o*3+0] + z1 * w0[o*3+1] + z2 * w0[o*3+2] + b0[o];
    h1[lq][o] = sinf(fr * v);
    for (int i = tid; i < ORDER * ORDER; i += 256) ws[i >> 6][i & 63] = w1[i];
    __syncthreads();

    float s = b1[o];
#pragma unroll 8
    for (int j = 0; j < ORDER; j++) s = fmaf(ws[o][j], h1[lq][j], s);
    const float h2v = sinf(fr * s);
    __syncthreads();

    h1[lq][o] = h2v;
    for (int i = tid; i < ORDER * ORDER; i += 256) ws[i >> 6][i & 63] = w2[i];
    __syncthreads();

    s = b2[o];
#pragma unroll 8
    for (int j = 0; j < ORDER; j++) s = fmaf(ws[o][j], h1[lq][j], s);
    g_h[(size_t)l * ORDER + o] = sinf(fr * s);
}

__global__ void __launch_bounds__(256)
filter_k_kernel(const float* __restrict__ w3)
{
    __shared__ float hs[32][ORDER + 1];
    const int l0 = blockIdx.x * 32, d0 = blockIdx.y * 32;
    const int tx = threadIdx.x, ty = threadIdx.y;

    for (int i = ty; i < 32; i += 8) {
        hs[i][tx]      = g_h[(size_t)(l0 + i) * ORDER + tx];
        hs[i][tx + 32] = g_h[(size_t)(l0 + i) * ORDER + tx + 32];
    }
    __syncthreads();

    const int l = l0 + tx;
    const float t = (float)l / (float)(LSEQ - 1);
    const float min_decay = -4.60517018598809136804f / 1.5f;
    const float max_decay = -4.60517018598809136804f / 0.3f;
    for (int di = ty; di < 32; di += 8) {
        const int d = d0 + di;
        float s = 0.f;
#pragma unroll 8
        for (int j = 0; j < ORDER; j++)
            s = fmaf(w3[(size_t)d * ORDER + j], hs[tx][j], s);
        const float delta = min_decay + (max_decay - min_decay) * (float)d / (float)(DMODEL - 1);
        g_k[(size_t)d * LSEQ + l] = s * expf(-t * fabsf(delta));
    }
}

// ---------------------------------------------------------------------------
// N=8192 FFT: three radix-16 register stages + radix-2 tail.
// XOR-swizzled smem (q = w ^ ((w>>4)&15)) -> fully bank-conflict-free.
// tw[t] = exp(-2*pi*i*t/8192), t in [0, 512)
// ---------------------------------------------------------------------------
#define SQ(w) ((w) ^ (((w) >> 4) & 15))

__device__ __forceinline__ float2 cmul(float2 a, float2 b) {
    return make_float2(a.x*b.x - a.y*b.y, a.x*b.y + a.y*b.x);
}

__device__ __forceinline__ void fft_init_tw(float2* tw)
{
    for (int i = threadIdx.x; i < 512; i += FFT_T) {
        float s, c;
        sincosf(-2.f * 3.14159265358979323846f * (float)i / (float)NFFT, &s, &c);
        tw[i] = make_float2(c, s);
    }
}

#define CMC(v, wr, wi) do { float _x=(v).x, _y=(v).y; \
    (v).x = _x*(wr) - _y*(wi); (v).y = _x*(wi) + _y*(wr); } while (0)

__device__ __forceinline__ void bf4(float2& a, float2& b, float2& c, float2& d)
{
    const float2 A = make_float2(a.x + c.x, a.y + c.y);
    const float2 B = make_float2(a.x - c.x, a.y - c.y);
    const float2 Cc = make_float2(b.x + d.x, b.y + d.y);
    const float2 D = make_float2(b.x - d.x, b.y - d.y);
    a = make_float2(A.x + Cc.x, A.y + Cc.y);
    c = make_float2(A.x - Cc.x, A.y - Cc.y);
    b = make_float2(B.x + D.y, B.y - D.x);   // B - iD
    d = make_float2(B.x - D.y, B.y + D.x);   // B + iD
}

// In-place 16-point DFT; output y[n] ends at x[4*(n&3) + (n>>2)]
__device__ __forceinline__ void dft16(float2* x)
{
    bf4(x[0], x[4], x[8],  x[12]);
    bf4(x[1], x[5], x[9],  x[13]);
    bf4(x[2], x[6], x[10], x[14]);
    bf4(x[3], x[7], x[11], x[15]);
    // stage twiddles: x[k2+4c] *= W16^(c*k2)
    const float C1 = 0.92387953251128674f, S1 = -0.38268343236508978f;
    const float C2 = 0.70710678118654757f, S2 = -0.70710678118654746f;
    const float C3 = 0.38268343236508984f, S3 = -0.92387953251128674f;
    const float C6 = -0.70710678118654746f, S6 = -0.70710678118654757f;
    const float C9 = -0.92387953251128674f, S9 =  0.38268343236508978f;
    CMC(x[5],  C1, S1);  CMC(x[9],  C2, S2);  CMC(x[13], C3, S3);
    CMC(x[6],  C2, S2);  { float tx = x[10].x; x[10].x = x[10].y; x[10].y = -tx; }  CMC(x[14], C6, S6);
    CMC(x[7],  C3, S3);  CMC(x[11], C6, S6);  CMC(x[15], C9, S9);
    bf4(x[0],  x[1],  x[2],  x[3]);
    bf4(x[4],  x[5],  x[6],  x[7]);
    bf4(x[8],  x[9],  x[10], x[11]);
    bf4(x[12], x[13], x[14], x[15]);
}

__device__ __forceinline__ void r16_stage(const float2* __restrict__ src,
                                          float2* __restrict__ dst,
                                          const float2* __restrict__ tw, int m)
{
    const int t = threadIdx.x;
    const int k = t & (m - 1);
    const int jm = t - k;
    float2 x[16];
#pragma unroll
    for (int c = 0; c < 16; c++) x[c] = src[SQ(t + 512 * c)];
    dft16(x);
    const float2 w1 = tw[jm];
    float2 wc = w1;
    const int ob = 16 * jm + k;
    dst[SQ(ob)] = x[0];
#pragma unroll
    for (int c = 1; c < 16; c++) {
        const float2 y = x[((c & 3) << 2) | (c >> 2)];
        dst[SQ(ob + c * m)] = cmul(y, wc);
        wc = cmul(wc, w1);
    }
}

// Result always lands back in A.
__device__ __forceinline__ float2* fft8192(float2* A, float2* B, const float2* tw)
{
    __syncthreads();
    r16_stage(A, B, tw, 1);    __syncthreads();
    r16_stage(B, A, tw, 16);   __syncthreads();
    r16_stage(A, B, tw, 256);  __syncthreads();
#pragma unroll 1
    for (int i = threadIdx.x; i < 4096; i += FFT_T) {
        const float2 a = B[SQ(i)];
        const float2 b = B[SQ(i + 4096)];
        A[SQ(i)]        = make_float2(a.x + b.x, a.y + b.y);
        A[SQ(i + 4096)] = make_float2(a.x - b.x, a.y - b.y);
    }
    __syncthreads();
    return A;
}

// FFT of filter k, two channels packed per block
__global__ void fftk_kernel()
{
    extern __shared__ float2 smem_fft[];
    float2* bufA = smem_fft;
    float2* bufB = bufA + NFFT;
    float2* tw   = bufB + NFFT;
    fft_init_tw(tw);

    const int d0 = blockIdx.x * 2;
    const float* k0 = g_k + (size_t)d0 * LSEQ;
    const float* k1 = k0 + LSEQ;
    for (int i = threadIdx.x; i < LSEQ; i += FFT_T) {
        bufA[SQ(i)]        = make_float2(k0[i], k1[i]);
        bufA[SQ(i + LSEQ)] = make_float2(0.f, 0.f);
    }
    float2* Z = fft8192(bufA, bufB, tw);

    const float hc = 0.5f / (float)NFFT;
    float2* o0 = g_Kf + (size_t)d0 * NFFT;
    float2* o1 = o0 + NFFT;
    for (int i = threadIdx.x; i < NFFT; i += FFT_T) {
        const int ir = (NFFT - i) & (NFFT - 1);
        const float2 A = Z[SQ(i)];
        const float2 Zr = Z[SQ(ir)];
        const float sx = A.x + Zr.x, sy = A.y - Zr.y;
        const float px = A.x - Zr.x, py = A.y + Zr.y;
        o0[i] = make_float2(sx * hc, sy * hc);
        o1[i] = make_float2(py * hc, -px * hc);
    }
}

// Fused FFT conv: both batches of one channel packed per block.
__global__ void fftconv_kernel(const float* __restrict__ fbias)
{
    extern __shared__ float2 smem_fft[];
    float2* bufA = smem_fft;
    float2* bufB = bufA + NFFT;
    float2* tw   = bufB + NFFT;
    fft_init_tw(tw);

    const int d = blockIdx.x;
    const float* v0 = g_vg + (size_t)d * LSEQ;
    const float* v1 = g_vg + ((size_t)DMODEL + d) * LSEQ;

    for (int i = threadIdx.x; i < LSEQ; i += FFT_T) {
        bufA[SQ(i)]        = make_float2(v0[i], v1[i]);
        bufA[SQ(i + LSEQ)] = make_float2(0.f, 0.f);
    }
    float2* Z = fft8192(bufA, bufB, tw);   // result in bufA

    const float2* kf = g_Kf + (size_t)d * NFFT;
    for (int i = threadIdx.x; i < NFFT; i += FFT_T) {
        const int ir = (NFFT - i) & (NFFT - 1);
        const float2 A = Z[SQ(i)];
        const float2 Zr = Z[SQ(ir)];
        const float u0x = 0.5f * (A.x + Zr.x), u0y = 0.5f * (A.y - Zr.y);
        const float px  = 0.5f * (A.x - Zr.x), py  = 0.5f * (A.y + Zr.y);
        const float u1x = py, u1y = -px;
        const float2 k = kf[i];
        const float y0x = u0x * k.x - u0y * k.y;
        const float y0y = u0x * k.y + u0y * k.x;
        const float y1x = u1x * k.x - u1y * k.y;
        const float y1y = u1x * k.y + u1y * k.x;
        bufB[SQ(i)] = make_float2(y0x - y1y, -(y0y + y1x));
    }
    float2* out = fft8192(bufB, bufA, tw);  // result in bufB

    const float fb = fbias[d];
    for (int i = threadIdx.x; i < LSEQ; i += FFT_T) {
        const size_t o0 = (size_t)d * LSEQ + i;
        const size_t o1 = ((size_t)DMODEL + d) * LSEQ + i;
        const float2 r = out[SQ(i)];
        g_y[o0] = (r.x + v0[i] * fb) * g_x0[o0];
        g_y[o1] = (-r.y + v1[i] * fb) * g_x0[o1];
    }
}

// ---------------------------------------------------------------------------
// Launch
// ---------------------------------------------------------------------------
extern "C" void kernel_launch(void* const* d_in, const int* in_sizes, int n_in,
                              void* d_out, int out_size)
{
    (void)in_sizes; (void)n_in; (void)out_size;
    const float* x     = (const float*)d_in[0];
    const float* ipw   = (const float*)d_in[1];
    const float* ipb   = (const float*)d_in[2];
    const float* sw    = (const float*)d_in[3];
    const float* sb    = (const float*)d_in[4];
    const float* w0    = (const float*)d_in[5];
    const float* b0    = (const float*)d_in[6];
    const float* freq  = (const float*)d_in[7];
    const float* w1    = (const float*)d_in[8];
    const float* b1    = (const float*)d_in[9];
    const float* w2    = (const float*)d_in[10];
    const float* b2    = (const float*)d_in[11];
    const float* w3    = (const float*)d_in[12];
    const float* fbias = (const float*)d_in[13];
    const float* opw   = (const float*)d_in[14];
    const float* opb   = (const float*)d_in[15];
    float* out = (float*)d_out;

    cudaFuncSetAttribute(fftk_kernel,    cudaFuncAttributeMaxDynamicSharedMemorySize, FFT_SMEM);
    cudaFuncSetAttribute(fftconv_kernel, cudaFuncAttributeMaxDynamicSharedMemorySize, FFT_SMEM);
    cudaFuncSetAttribute(gemm_tc_kernel, cudaFuncAttributeMaxDynamicSharedMemorySize, GM_SMEM);

    __nv_bfloat16 *p_ah, *p_al, *p_w1h, *p_w1l, *p_w2h, *p_w2l;
    cudaGetSymbolAddress((void**)&p_ah,  g_ah);
    cudaGetSymbolAddress((void**)&p_al,  g_al);
    cudaGetSymbolAddress((void**)&p_w1h, g_w1h);
    cudaGetSymbolAddress((void**)&p_w1l, g_w1l);
    cudaGetSymbolAddress((void**)&p_w2h, g_w2h);
    cudaGetSymbolAddress((void**)&p_w2l, g_w2l);
    float* p_u; cudaGetSymbolAddress((void**)&p_u, g_u);

    {
        const int n4x = (BATCH*LSEQ*DMODEL)/4;
        split_kernel<<<(n4x+255)/256, 256>>>((const float4*)x,
            (__nv_bfloat162*)p_ah, (__nv_bfloat162*)p_al, n4x);
        const int n4w1 = (D3*DMODEL)/4;
        split_kernel<<<(n4w1+255)/256, 256>>>((const float4*)ipw,
            (__nv_bfloat162*)p_w1h, (__nv_bfloat162*)p_w1l, n4w1);
        const int n4w2 = (DMODEL*DMODEL)/4;
        split_kernel<<<(n4w2+255)/256, 256>>>((const float4*)opw,
            (__nv_bfloat162*)p_w2h, (__nv_bfloat162*)p_w2l, n4w2);
    }

    gemm_tc_kernel<<<dim3(D3/128, (BATCH*LSEQ)/128, 1), 256, GM_SMEM>>>(
        p_ah, p_al, p_w1h, p_w1l, ipb, p_u, D3, DMODEL, 0, 0);

    shortconv_kernel<<<dim3(LSEQ/32, DMODEL/32, BATCH), dim3(32, 8)>>>(sw, sb);

    filter_h_kernel<<<LSEQ/4, dim3(ORDER, 4)>>>(w0, b0, freq, w1, b1, w2, b2);
    filter_k_kernel<<<dim3(LSEQ/32, DMODEL/32), dim3(32, 8)>>>(w3);

    fftk_kernel<<<DMODEL/2, FFT_T, FFT_SMEM>>>();

    fftconv_kernel<<<DMODEL, FFT_T, FFT_SMEM>>>(fbias);

    transsplit_kernel<<<dim3(LSEQ/32, DMODEL/32, BATCH), dim3(32, 8)>>>();

    gemm_tc_kernel<<<dim3(DMODEL/128, LSEQ/128, BATCH), 256, GM_SMEM>>>(
        p_ah, p_al, p_w2h, p_w2l, opb, out, DMODEL, DMODEL,
        (size_t)LSEQ*DMODEL, (size_t)LSEQ*DMODEL);
}

// round 6
// speedup vs baseline: 3.1427x; 1.1439x over previous
#include <cuda_runtime.h>
#include <cuda_bf16.h>
#include <math.h>
#include <stdint.h>

#define BATCH 2
#define LSEQ 4096
#define DMODEL 2048
#define D3 (3*DMODEL)
#define ORDER 64
#define NFFT 8192
#define NHALF 4096
#define FFT_T 512
#define FFT_SMEM ((2*NFFT + 512) * (int)sizeof(float2))   // 135168 B

// ---------------------------------------------------------------------------
// Scratch (device globals)
// ---------------------------------------------------------------------------
__device__ float  g_u [(size_t)BATCH*LSEQ*D3];
__device__ float  g_x0[(size_t)BATCH*DMODEL*LSEQ];
__device__ float  g_vg[(size_t)BATCH*DMODEL*LSEQ];
__device__ float  g_y [(size_t)BATCH*DMODEL*LSEQ];
__device__ float  g_h [(size_t)LSEQ*ORDER];
__device__ float  g_k [(size_t)DMODEL*LSEQ];
__device__ float2 g_Kf[(size_t)DMODEL*NFFT];

__device__ __nv_bfloat16 g_ah [(size_t)BATCH*LSEQ*DMODEL];
__device__ __nv_bfloat16 g_al [(size_t)BATCH*LSEQ*DMODEL];
__device__ __nv_bfloat16 g_w1h[(size_t)D3*DMODEL];
__device__ __nv_bfloat16 g_w1l[(size_t)D3*DMODEL];
__device__ __nv_bfloat16 g_w2h[(size_t)DMODEL*DMODEL];
__device__ __nv_bfloat16 g_w2l[(size_t)DMODEL*DMODEL];

// ---------------------------------------------------------------------------
// Warp-MMA GEMM: 3-stage cp.async pipeline, XOR-swizzled smem, 2 CTAs/SM
// ---------------------------------------------------------------------------
#define GK_CHUNK 32
#define ARR_BYTES 8192
#define STAGE_BYTES (4*ARR_BYTES)
#define NSTAGE 3
#define GM_SMEM (NSTAGE*STAGE_BYTES)      // 98304 B

__device__ __forceinline__ uint32_t sw_off(int r, int cseg) {
    return (uint32_t)(r * 64 + ((cseg ^ ((r >> 1) & 3)) << 4));
}

__device__ __forceinline__ void cpa16(uint32_t s, const void* g) {
    asm volatile("cp.async.cg.shared.global [%0], [%1], 16;" :: "r"(s), "l"(g));
}
#define CP_COMMIT() asm volatile("cp.async.commit_group;" ::: "memory")
#define CP_WAIT1()  asm volatile("cp.async.wait_group 1;" ::: "memory")

#define LDSM_X4(r, addr) \
    asm volatile("ldmatrix.sync.aligned.m8n8.x4.shared.b16 {%0,%1,%2,%3}, [%4];" \
        : "=r"((r)[0]), "=r"((r)[1]), "=r"((r)[2]), "=r"((r)[3]) : "r"(addr))

#define MMA16816(c, a, b) \
    asm volatile("mma.sync.aligned.m16n8k16.row.col.f32.bf16.bf16.f32 " \
        "{%0,%1,%2,%3}, {%4,%5,%6,%7}, {%8,%9}, {%0,%1,%2,%3};" \
        : "+f"((c)[0]), "+f"((c)[1]), "+f"((c)[2]), "+f"((c)[3]) \
        : "r"((a)[0]), "r"((a)[1]), "r"((a)[2]), "r"((a)[3]), \
          "r"((b)[0]), "r"((b)[1]))

__global__ void __launch_bounds__(256, 2)
gemm_tc_kernel(const __nv_bfloat16* __restrict__ Ah, const __nv_bfloat16* __restrict__ Al,
               const __nv_bfloat16* __restrict__ Wh, const __nv_bfloat16* __restrict__ Wl,
               const float* __restrict__ bias, float* __restrict__ C,
               int Ntot, int K, size_t strideA, size_t strideC)
{
    extern __shared__ char smem[];
    const uint32_t sbase = (uint32_t)__cvta_generic_to_shared(smem);
    const int tid  = threadIdx.x;
    const int lane = tid & 31;
    const int wid  = tid >> 5;
    const int wm   = wid & 3;
    const int wn   = wid >> 2;

    const int z = blockIdx.z;
    const __nv_bfloat16* Ahb = Ah + (size_t)z * strideA;
    const __nv_bfloat16* Alb = Al + (size_t)z * strideA;
    float* Cb = C + (size_t)z * strideC;

    const int col0 = blockIdx.x * 128;
    const int row0 = blockIdx.y * 128;
    const int nchunk = K / GK_CHUNK;

    float acc[2][8][4];
#pragma unroll
    for (int i = 0; i < 2; i++)
#pragma unroll
        for (int j = 0; j < 8; j++)
#pragma unroll
            for (int q = 0; q < 4; q++) acc[i][j][q] = 0.f;

    auto load_stage = [&](int slot, int k0) {
        const uint32_t sb = sbase + (uint32_t)(slot * STAGE_BYTES);
#pragma unroll
        for (int i = 0; i < 2; i++) {
            const int seg = tid + i * 256;
            const int r = seg >> 2, c = seg & 3;
            const size_t ga = (size_t)(row0 + r) * K + k0 + c * 8;
            const size_t gb = (size_t)(col0 + r) * K + k0 + c * 8;
            const uint32_t so = sw_off(r, c);
            cpa16(sb + so,               Ahb + ga);
            cpa16(sb + so + ARR_BYTES,   Alb + ga);
            cpa16(sb + so + 2*ARR_BYTES, Wh  + gb);
            cpa16(sb + so + 3*ARR_BYTES, Wl  + gb);
        }
    };

    load_stage(0, 0);        CP_COMMIT();
    load_stage(1, GK_CHUNK); CP_COMMIT();

    const int a_row  = lane & 15;
    const int a_half = lane >> 4;
    const int b_row  = (((lane >> 3) & 3) >> 1) * 8 + (lane & 7);
    const int b_half = (lane >> 3) & 1;

    int slot = 0;
    for (int c = 0; c < nchunk; c++) {
        CP_WAIT1();
        __syncthreads();
        if (c + 2 < nchunk) {
            const int nslot = (slot + 2 >= NSTAGE) ? (slot + 2 - NSTAGE) : (slot + 2);
            load_stage(nslot, (c + 2) * GK_CHUNK);
        }
        CP_COMMIT();

        const uint32_t stb = sbase + (uint32_t)(slot * STAGE_BYTES);
#pragma unroll
        for (int step = 0; step < 2; step++) {
            uint32_t ah[2][4], al[2][4];
#pragma unroll
            for (int mt = 0; mt < 2; mt++) {
                const int r = wm*32 + mt*16 + a_row;
                const uint32_t off = sw_off(r, step*2 + a_half);
                LDSM_X4(ah[mt], stb + off);
                LDSM_X4(al[mt], stb + ARR_BYTES + off);
            }
            uint32_t bh[8][2], bl[8][2];
#pragma unroll
            for (int p = 0; p < 4; p++) {
                const int r = wn*64 + p*16 + b_row;
                const uint32_t off = sw_off(r, step*2 + b_half);
                uint32_t t[4];
                LDSM_X4(t, stb + 2*ARR_BYTES + off);
                bh[p*2][0]=t[0]; bh[p*2][1]=t[1]; bh[p*2+1][0]=t[2]; bh[p*2+1][1]=t[3];
                LDSM_X4(t, stb + 3*ARR_BYTES + off);
                bl[p*2][0]=t[0]; bl[p*2][1]=t[1]; bl[p*2+1][0]=t[2]; bl[p*2+1][1]=t[3];
            }
#pragma unroll
            for (int mt = 0; mt < 2; mt++)
#pragma unroll
                for (int nt = 0; nt < 8; nt++) {
                    MMA16816(acc[mt][nt], ah[mt], bh[nt]);
                    MMA16816(acc[mt][nt], ah[mt], bl[nt]);
                    MMA16816(acc[mt][nt], al[mt], bh[nt]);
                }
        }
        slot = (slot + 1 == NSTAGE) ? 0 : slot + 1;
    }

#pragma unroll
    for (int mt = 0; mt < 2; mt++) {
        const int r0g = row0 + wm*32 + mt*16 + (lane >> 2);
#pragma unroll
        for (int nt = 0; nt < 8; nt++) {
            const int col = col0 + wn*64 + nt*8 + (lane & 3)*2;
            const float b0 = bias[col], b1 = bias[col+1];
            float2 v0 = make_float2(acc[mt][nt][0] + b0, acc[mt][nt][1] + b1);
            float2 v1 = make_float2(acc[mt][nt][2] + b0, acc[mt][nt][3] + b1);
            *(float2*)(Cb + (size_t)r0g       * Ntot + col) = v0;
            *(float2*)(Cb + (size_t)(r0g + 8) * Ntot + col) = v1;
        }
    }
}

// ---------------------------------------------------------------------------
// fp32 -> bf16 hi/lo split
// ---------------------------------------------------------------------------
__global__ void __launch_bounds__(256)
split_kernel(const float4* __restrict__ src, __nv_bfloat162* __restrict__ hi,
             __nv_bfloat162* __restrict__ lo, int n4)
{
    const int i = blockIdx.x * 256 + threadIdx.x;
    if (i >= n4) return;
    const float4 v = src[i];
    __nv_bfloat162 h0 = __floats2bfloat162_rn(v.x, v.y);
    __nv_bfloat162 h1 = __floats2bfloat162_rn(v.z, v.w);
    float2 f0 = __bfloat1622float2(h0);
    float2 f1 = __bfloat1622float2(h1);
    hi[i*2+0] = h0;
    hi[i*2+1] = h1;
    lo[i*2+0] = __floats2bfloat162_rn(v.x - f0.x, v.y - f0.y);
    lo[i*2+1] = __floats2bfloat162_rn(v.z - f1.x, v.w - f1.y);
}

__global__ void __launch_bounds__(256)
transsplit_kernel()
{
    __shared__ float t[32][33];
    const int b = blockIdx.z, d0 = blockIdx.y * 32, l0 = blockIdx.x * 32;
    const int tx = threadIdx.x, ty = threadIdx.y;
    for (int dy = ty; dy < 32; dy += 8)
        t[dy][tx] = g_y[((size_t)b * DMODEL + d0 + dy) * LSEQ + l0 + tx];
    __syncthreads();
    for (int ly = ty; ly < 32; ly += 8) {
        const float v = t[tx][ly];
        const size_t o = ((size_t)b * LSEQ + l0 + ly) * DMODEL + d0 + tx;
        const __nv_bfloat16 h = __float2bfloat16(v);
        g_ah[o] = h;
        g_al[o] = __float2bfloat16(v - __bfloat162float(h));
    }
}

// ---------------------------------------------------------------------------
// Short conv + transpose + gate
// ---------------------------------------------------------------------------
__global__ void __launch_bounds__(256)
shortconv_kernel(const float* __restrict__ sw, const float* __restrict__ sb)
{
    __shared__ float su[3][34][33];
    const int b = blockIdx.z, l0 = blockIdx.x * 32, d0 = blockIdx.y * 32;
    const int tx = threadIdx.x, ty = threadIdx.y;

#pragma unroll
    for (int g = 0; g < 3; g++)
        for (int li = ty; li < 34; li += 8) {
            const int l = l0 + li - 2;
            su[g][li][tx] = (l >= 0)
                ? g_u[((size_t)b * LSEQ + l) * D3 + g * DMODEL + d0 + tx] : 0.f;
        }
    __syncthreads();

    const int l = l0 + tx;
    for (int di = ty; di < 32; di += 8) {
        const int d = d0 + di;
        float r[3];
#pragma unroll
        for (int g = 0; g < 3; g++) {
            const int c = g * DMODEL + d;
            r[g] = sw[c*3+0] * su[g][tx][di]
                 + sw[c*3+1] * su[g][tx+1][di]
                 + sw[c*3+2] * su[g][tx+2][di]
                 + sb[c];
        }
        const size_t o = ((size_t)b * DMODEL + d) * LSEQ + l;
        g_x0[o] = r[0];
        g_vg[o] = r[1] * r[2];
    }
}

// ---------------------------------------------------------------------------
// Filter MLP
// ---------------------------------------------------------------------------
__global__ void __launch_bounds__(256)
filter_h_kernel(const float* __restrict__ w0, const float* __restrict__ b0,
                const float* __restrict__ freq,
                const float* __restrict__ w1, const float* __restrict__ b1,
                const float* __restrict__ w2, const float* __restrict__ b2)
{
    __shared__ float ws[ORDER][ORDER + 1];
    __shared__ float h1[4][ORDER + 1];
    const int o  = threadIdx.x;
    const int lq = threadIdx.y;
    const int l  = blockIdx.x * 4 + lq;
    const int tid = lq * ORDER + o;

    const float t   = (float)l / (float)(LSEQ - 1);
    const float wl  = 2.f * 3.14159265358979323846f * (float)l / (float)LSEQ;
    const float ang = 1e-4f * wl;
    const float z1 = cosf(ang), z2 = -sinf(ang);
    const float fr = freq[o];
    float v = t * w0[o*3+0] + z1 * w0[o*3+1] + z2 * w0[o*3+2] + b0[o];
    h1[lq][o] = sinf(fr * v);
    for (int i = tid; i < ORDER * ORDER; i += 256) ws[i >> 6][i & 63] = w1[i];
    __syncthreads();

    float s = b1[o];
#pragma unroll 8
    for (int j = 0; j < ORDER; j++) s = fmaf(ws[o][j], h1[lq][j], s);
    const float h2v = sinf(fr * s);
    __syncthreads();

    h1[lq][o] = h2v;
    for (int i = tid; i < ORDER * ORDER; i += 256) ws[i >> 6][i & 63] = w2[i];
    __syncthreads();

    s = b2[o];
#pragma unroll 8
    for (int j = 0; j < ORDER; j++) s = fmaf(ws[o][j], h1[lq][j], s);
    g_h[(size_t)l * ORDER + o] = sinf(fr * s);
}

__global__ void __launch_bounds__(256)
filter_k_kernel(const float* __restrict__ w3)
{
    __shared__ float hs[32][ORDER + 1];
    const int l0 = blockIdx.x * 32, d0 = blockIdx.y * 32;
    const int tx = threadIdx.x, ty = threadIdx.y;

    for (int i = ty; i < 32; i += 8) {
        hs[i][tx]      = g_h[(size_t)(l0 + i) * ORDER + tx];
        hs[i][tx + 32] = g_h[(size_t)(l0 + i) * ORDER + tx + 32];
    }
    __syncthreads();

    const int l = l0 + tx;
    const float t = (float)l / (float)(LSEQ - 1);
    const float min_decay = -4.60517018598809136804f / 1.5f;
    const float max_decay = -4.60517018598809136804f / 0.3f;
    for (int di = ty; di < 32; di += 8) {
        const int d = d0 + di;
        float s = 0.f;
#pragma unroll 8
        for (int j = 0; j < ORDER; j++)
            s = fmaf(w3[(size_t)d * ORDER + j], hs[tx][j], s);
        const float delta = min_decay + (max_decay - min_decay) * (float)d / (float)(DMODEL - 1);
        g_k[(size_t)d * LSEQ + l] = s * expf(-t * fabsf(delta));
    }
}

// ---------------------------------------------------------------------------
// N=8192 FFT: three radix-16 register stages + radix-2 tail (XOR swizzle)
// ---------------------------------------------------------------------------
#define SQ(w) ((w) ^ (((w) >> 4) & 15))

__device__ __forceinline__ float2 cmul(float2 a, float2 b) {
    return make_float2(a.x*b.x - a.y*b.y, a.x*b.y + a.y*b.x);
}

__device__ __forceinline__ void fft_init_tw(float2* tw)
{
    for (int i = threadIdx.x; i < 512; i += FFT_T) {
        float s, c;
        sincosf(-2.f * 3.14159265358979323846f * (float)i / (float)NFFT, &s, &c);
        tw[i] = make_float2(c, s);
    }
}

#define CMC(v, wr, wi) do { float _x=(v).x, _y=(v).y; \
    (v).x = _x*(wr) - _y*(wi); (v).y = _x*(wi) + _y*(wr); } while (0)

__device__ __forceinline__ void bf4(float2& a, float2& b, float2& c, float2& d)
{
    const float2 A = make_float2(a.x + c.x, a.y + c.y);
    const float2 B = make_float2(a.x - c.x, a.y - c.y);
    const float2 Cc = make_float2(b.x + d.x, b.y + d.y);
    const float2 D = make_float2(b.x - d.x, b.y - d.y);
    a = make_float2(A.x + Cc.x, A.y + Cc.y);
    c = make_float2(A.x - Cc.x, A.y - Cc.y);
    b = make_float2(B.x + D.y, B.y - D.x);
    d = make_float2(B.x - D.y, B.y + D.x);
}

__device__ __forceinline__ void dft16(float2* x)
{
    bf4(x[0], x[4], x[8],  x[12]);
    bf4(x[1], x[5], x[9],  x[13]);
    bf4(x[2], x[6], x[10], x[14]);
    bf4(x[3], x[7], x[11], x[15]);
    const float C1 = 0.92387953251128674f, S1 = -0.38268343236508978f;
    const float C2 = 0.70710678118654757f, S2 = -0.70710678118654746f;
    const float C3 = 0.38268343236508984f, S3 = -0.92387953251128674f;
    const float C6 = -0.70710678118654746f, S6 = -0.70710678118654757f;
    const float C9 = -0.92387953251128674f, S9 =  0.38268343236508978f;
    CMC(x[5],  C1, S1);  CMC(x[9],  C2, S2);  CMC(x[13], C3, S3);
    CMC(x[6],  C2, S2);  { float tx = x[10].x; x[10].x = x[10].y; x[10].y = -tx; }  CMC(x[14], C6, S6);
    CMC(x[7],  C3, S3);  CMC(x[11], C6, S6);  CMC(x[15], C9, S9);
    bf4(x[0],  x[1],  x[2],  x[3]);
    bf4(x[4],  x[5],  x[6],  x[7]);
    bf4(x[8],  x[9],  x[10], x[11]);
    bf4(x[12], x[13], x[14], x[15]);
}

__device__ __forceinline__ void r16_stage(const float2* __restrict__ src,
                                          float2* __restrict__ dst,
                                          const float2* __restrict__ tw, int m)
{
    const int t = threadIdx.x;
    const int k = t & (m - 1);
    const int jm = t - k;
    float2 x[16];
#pragma unroll
    for (int c = 0; c < 16; c++) x[c] = src[SQ(t + 512 * c)];
    dft16(x);
    const float2 w1 = tw[jm];
    float2 wc = w1;
    const int ob = 16 * jm + k;
    dst[SQ(ob)] = x[0];
#pragma unroll
    for (int c = 1; c < 16; c++) {
        const float2 y = x[((c & 3) << 2) | (c >> 2)];
        dst[SQ(ob + c * m)] = cmul(y, wc);
        wc = cmul(wc, w1);
    }
}

__device__ __forceinline__ float2* fft8192(float2* A, float2* B, const float2* tw)
{
    __syncthreads();
    r16_stage(A, B, tw, 1);    __syncthreads();
    r16_stage(B, A, tw, 16);   __syncthreads();
    r16_stage(A, B, tw, 256);  __syncthreads();
#pragma unroll 1
    for (int i = threadIdx.x; i < 4096; i += FFT_T) {
        const float2 a = B[SQ(i)];
        const float2 b = B[SQ(i + 4096)];
        A[SQ(i)]        = make_float2(a.x + b.x, a.y + b.y);
        A[SQ(i + 4096)] = make_float2(a.x - b.x, a.y - b.y);
    }
    __syncthreads();
    return A;
}

__global__ void fftk_kernel()
{
    extern __shared__ float2 smem_fft[];
    float2* bufA = smem_fft;
    float2* bufB = bufA + NFFT;
    float2* tw   = bufB + NFFT;
    fft_init_tw(tw);

    const int d0 = blockIdx.x * 2;
    const float* k0 = g_k + (size_t)d0 * LSEQ;
    const float* k1 = k0 + LSEQ;
    for (int i = threadIdx.x; i < LSEQ; i += FFT_T) {
        bufA[SQ(i)]        = make_float2(k0[i], k1[i]);
        bufA[SQ(i + LSEQ)] = make_float2(0.f, 0.f);
    }
    float2* Z = fft8192(bufA, bufB, tw);

    const float hc = 0.5f / (float)NFFT;
    float2* o0 = g_Kf + (size_t)d0 * NFFT;
    float2* o1 = o0 + NFFT;
    for (int i = threadIdx.x; i < NFFT; i += FFT_T) {
        const int ir = (NFFT - i) & (NFFT - 1);
        const float2 A = Z[SQ(i)];
        const float2 Zr = Z[SQ(ir)];
        const float sx = A.x + Zr.x, sy = A.y - Zr.y;
        const float px = A.x - Zr.x, py = A.y + Zr.y;
        o0[i] = make_float2(sx * hc, sy * hc);
        o1[i] = make_float2(py * hc, -px * hc);
    }
}

__global__ void fftconv_kernel(const float* __restrict__ fbias)
{
    extern __shared__ float2 smem_fft[];
    float2* bufA = smem_fft;
    float2* bufB = bufA + NFFT;
    float2* tw   = bufB + NFFT;
    fft_init_tw(tw);

    const int d = blockIdx.x;
    const float* v0 = g_vg + (size_t)d * LSEQ;
    const float* v1 = g_vg + ((size_t)DMODEL + d) * LSEQ;

    for (int i = threadIdx.x; i < LSEQ; i += FFT_T) {
        bufA[SQ(i)]        = make_float2(v0[i], v1[i]);
        bufA[SQ(i + LSEQ)] = make_float2(0.f, 0.f);
    }
    float2* Z = fft8192(bufA, bufB, tw);

    const float2* kf = g_Kf + (size_t)d * NFFT;
    for (int i = threadIdx.x; i < NFFT; i += FFT_T) {
        const int ir = (NFFT - i) & (NFFT - 1);
        const float2 A = Z[SQ(i)];
        const float2 Zr = Z[SQ(ir)];
        const float u0x = 0.5f * (A.x + Zr.x), u0y = 0.5f * (A.y - Zr.y);
        const float px  = 0.5f * (A.x - Zr.x), py  = 0.5f * (A.y + Zr.y);
        const float u1x = py, u1y = -px;
        const float2 k = kf[i];
        const float y0x = u0x * k.x - u0y * k.y;
        const float y0y = u0x * k.y + u0y * k.x;
        const float y1x = u1x * k.x - u1y * k.y;
        const float y1y = u1x * k.y + u1y * k.x;
        bufB[SQ(i)] = make_float2(y0x - y1y, -(y0y + y1x));
    }
    float2* out = fft8192(bufB, bufA, tw);

    const float fb = fbias[d];
    for (int i = threadIdx.x; i < LSEQ; i += FFT_T) {
        const size_t o0 = (size_t)d * LSEQ + i;
        const size_t o1 = ((size_t)DMODEL + d) * LSEQ + i;
        const float2 r = out[SQ(i)];
        g_y[o0] = (r.x + v0[i] * fb) * g_x0[o0];
        g_y[o1] = (-r.y + v1[i] * fb) * g_x0[o1];
    }
}

// ---------------------------------------------------------------------------
// Launch
// ---------------------------------------------------------------------------
extern "C" void kernel_launch(void* const* d_in, const int* in_sizes, int n_in,
                              void* d_out, int out_size)
{
    (void)in_sizes; (void)n_in; (void)out_size;
    const float* x     = (const float*)d_in[0];
    const float* ipw   = (const float*)d_in[1];
    const float* ipb   = (const float*)d_in[2];
    const float* sw    = (const float*)d_in[3];
    const float* sb    = (const float*)d_in[4];
    const float* w0    = (const float*)d_in[5];
    const float* b0    = (const float*)d_in[6];
    const float* freq  = (const float*)d_in[7];
    const float* w1    = (const float*)d_in[8];
    const float* b1    = (const float*)d_in[9];
    const float* w2    = (const float*)d_in[10];
    const float* b2    = (const float*)d_in[11];
    const float* w3    = (const float*)d_in[12];
    const float* fbias = (const float*)d_in[13];
    const float* opw   = (const float*)d_in[14];
    const float* opb   = (const float*)d_in[15];
    float* out = (float*)d_out;

    cudaFuncSetAttribute(fftk_kernel,    cudaFuncAttributeMaxDynamicSharedMemorySize, FFT_SMEM);
    cudaFuncSetAttribute(fftconv_kernel, cudaFuncAttributeMaxDynamicSharedMemorySize, FFT_SMEM);
    cudaFuncSetAttribute(gemm_tc_kernel, cudaFuncAttributeMaxDynamicSharedMemorySize, GM_SMEM);

    __nv_bfloat16 *p_ah, *p_al, *p_w1h, *p_w1l, *p_w2h, *p_w2l;
    cudaGetSymbolAddress((void**)&p_ah,  g_ah);
    cudaGetSymbolAddress((void**)&p_al,  g_al);
    cudaGetSymbolAddress((void**)&p_w1h, g_w1h);
    cudaGetSymbolAddress((void**)&p_w1l, g_w1l);
    cudaGetSymbolAddress((void**)&p_w2h, g_w2h);
    cudaGetSymbolAddress((void**)&p_w2l, g_w2l);
    float* p_u; cudaGetSymbolAddress((void**)&p_u, g_u);

    {
        const int n4x = (BATCH*LSEQ*DMODEL)/4;
        split_kernel<<<(n4x+255)/256, 256>>>((const float4*)x,
            (__nv_bfloat162*)p_ah, (__nv_bfloat162*)p_al, n4x);
        const int n4w1 = (D3*DMODEL)/4;
        split_kernel<<<(n4w1+255)/256, 256>>>((const float4*)ipw,
            (__nv_bfloat162*)p_w1h, (__nv_bfloat162*)p_w1l, n4w1);
        const int n4w2 = (DMODEL*DMODEL)/4;
        split_kernel<<<(n4w2+255)/256, 256>>>((const float4*)opw,
            (__nv_bfloat162*)p_w2h, (__nv_bfloat162*)p_w2l, n4w2);
    }

    gemm_tc_kernel<<<dim3(D3/128, (BATCH*LSEQ)/128, 1), 256, GM_SMEM>>>(
        p_ah, p_al, p_w1h, p_w1l, ipb, p_u, D3, DMODEL, 0, 0);

    shortconv_kernel<<<dim3(LSEQ/32, DMODEL/32, BATCH), dim3(32, 8)>>>(sw, sb);

    filter_h_kernel<<<LSEQ/4, dim3(ORDER, 4)>>>(w0, b0, freq, w1, b1, w2, b2);
    filter_k_kernel<<<dim3(LSEQ/32, DMODEL/32), dim3(32, 8)>>>(w3);

    fftk_kernel<<<DMODEL/2, FFT_T, FFT_SMEM>>>();

    fftconv_kernel<<<DMODEL, FFT_T, FFT_SMEM>>>(fbias);

    transsplit_kernel<<<dim3(LSEQ/32, DMODEL/32, BATCH), dim3(32, 8)>>>();

    gemm_tc_kernel<<<dim3(DMODEL/128, LSEQ/128, BATCH), 256, GM_SMEM>>>(
        p_ah, p_al, p_w2h, p_w2l, opb, out, DMODEL, DMODEL,
        (size_t)LSEQ*DMODEL, (size_t)LSEQ*DMODEL);
}

// round 7
// speedup vs baseline: 5.6307x; 1.7917x over previous
#include <cuda_runtime.h>
#include <cuda_fp16.h>
#include <math.h>
#include <stdint.h>

#define BATCH 2
#define LSEQ 4096
#define DMODEL 2048
#define D3 (3*DMODEL)
#define ORDER 64
#define NFFT 8192
#define NHALF 4096
#define FFT_T 512
#define FFT_SMEM ((2*NFFT + 512) * (int)sizeof(float2))   // 135168 B

// ---------------------------------------------------------------------------
// Scratch (device globals)
// ---------------------------------------------------------------------------
__device__ float  g_u [(size_t)BATCH*LSEQ*D3];
__device__ float  g_x0[(size_t)BATCH*DMODEL*LSEQ];
__device__ float  g_vg[(size_t)BATCH*DMODEL*LSEQ];
__device__ float  g_y [(size_t)BATCH*DMODEL*LSEQ];
__device__ float  g_h [(size_t)LSEQ*ORDER];
__device__ float  g_k [(size_t)DMODEL*LSEQ];
__device__ float2 g_Kf[(size_t)DMODEL*NFFT];

__device__ __half g_a  [(size_t)BATCH*LSEQ*DMODEL];   // fp16 A (x, then y^T)
__device__ __half g_w1 [(size_t)D3*DMODEL];
__device__ __half g_w2 [(size_t)DMODEL*DMODEL];

// ---------------------------------------------------------------------------
// Warp-MMA GEMM (fp16, single term): 3-stage cp.async, XOR swizzle, 2 CTAs/SM
// Tile 128x128, K-chunk 64. Stage: A 16K | B 16K.
// ---------------------------------------------------------------------------
#define GK_CHUNK 64
#define ARR_BYTES 16384
#define STAGE_BYTES (2*ARR_BYTES)
#define NSTAGE 3
#define GM_SMEM (NSTAGE*STAGE_BYTES)      // 98304 B

__device__ __forceinline__ uint32_t sw_off(int r, int cseg) {
    return (uint32_t)(r * 128 + ((cseg ^ (r & 7)) << 4));
}

__device__ __forceinline__ void cpa16(uint32_t s, const void* g) {
    asm volatile("cp.async.cg.shared.global [%0], [%1], 16;" :: "r"(s), "l"(g));
}
#define CP_COMMIT() asm volatile("cp.async.commit_group;" ::: "memory")
#define CP_WAIT1()  asm volatile("cp.async.wait_group 1;" ::: "memory")

#define LDSM_X4(r, addr) \
    asm volatile("ldmatrix.sync.aligned.m8n8.x4.shared.b16 {%0,%1,%2,%3}, [%4];" \
        : "=r"((r)[0]), "=r"((r)[1]), "=r"((r)[2]), "=r"((r)[3]) : "r"(addr))

#define MMA16816(c, a, b) \
    asm volatile("mma.sync.aligned.m16n8k16.row.col.f32.f16.f16.f32 " \
        "{%0,%1,%2,%3}, {%4,%5,%6,%7}, {%8,%9}, {%0,%1,%2,%3};" \
        : "+f"((c)[0]), "+f"((c)[1]), "+f"((c)[2]), "+f"((c)[3]) \
        : "r"((a)[0]), "r"((a)[1]), "r"((a)[2]), "r"((a)[3]), \
          "r"((b)[0]), "r"((b)[1]))

__global__ void __launch_bounds__(256, 2)
gemm_tc_kernel(const __half* __restrict__ A, const __half* __restrict__ W,
               const float* __restrict__ bias, float* __restrict__ C,
               int Ntot, int K, size_t strideA, size_t strideC)
{
    extern __shared__ char smem[];
    const uint32_t sbase = (uint32_t)__cvta_generic_to_shared(smem);
    const int tid  = threadIdx.x;
    const int lane = tid & 31;
    const int wid  = tid >> 5;
    const int wm   = wid & 3;
    const int wn   = wid >> 2;

    const int z = blockIdx.z;
    const __half* Ab = A + (size_t)z * strideA;
    float* Cb = C + (size_t)z * strideC;

    const int col0 = blockIdx.x * 128;
    const int row0 = blockIdx.y * 128;
    const int nchunk = K / GK_CHUNK;

    float acc[2][8][4];
#pragma unroll
    for (int i = 0; i < 2; i++)
#pragma unroll
        for (int j = 0; j < 8; j++)
#pragma unroll
            for (int q = 0; q < 4; q++) acc[i][j][q] = 0.f;

    auto load_stage = [&](int slot, int k0) {
        const uint32_t sb = sbase + (uint32_t)(slot * STAGE_BYTES);
#pragma unroll
        for (int i = 0; i < 4; i++) {
            const int seg = tid + i * 256;         // 0..1023
            const int r = seg >> 3, c = seg & 7;
            const uint32_t so = sw_off(r, c);
            cpa16(sb + so,             Ab + (size_t)(row0 + r) * K + k0 + c * 8);
            cpa16(sb + so + ARR_BYTES, W  + (size_t)(col0 + r) * K + k0 + c * 8);
        }
    };

    load_stage(0, 0);        CP_COMMIT();
    load_stage(1, GK_CHUNK); CP_COMMIT();

    const int a_row  = lane & 15;
    const int a_half = lane >> 4;
    const int b_row  = (((lane >> 3) & 3) >> 1) * 8 + (lane & 7);
    const int b_half = (lane >> 3) & 1;

    int slot = 0;
    for (int c = 0; c < nchunk; c++) {
        CP_WAIT1();
        __syncthreads();
        if (c + 2 < nchunk) {
            const int nslot = (slot + 2 >= NSTAGE) ? (slot + 2 - NSTAGE) : (slot + 2);
            load_stage(nslot, (c + 2) * GK_CHUNK);
        }
        CP_COMMIT();

        const uint32_t stb = sbase + (uint32_t)(slot * STAGE_BYTES);
#pragma unroll
        for (int step = 0; step < 4; step++) {
            uint32_t af[2][4];
#pragma unroll
            for (int mt = 0; mt < 2; mt++) {
                const int r = wm*32 + mt*16 + a_row;
                LDSM_X4(af[mt], stb + sw_off(r, step*2 + a_half));
            }
            uint32_t bf[8][2];
#pragma unroll
            for (int p = 0; p < 4; p++) {
                const int r = wn*64 + p*16 + b_row;
                uint32_t t[4];
                LDSM_X4(t, stb + ARR_BYTES + sw_off(r, step*2 + b_half));
                bf[p*2][0]=t[0]; bf[p*2][1]=t[1]; bf[p*2+1][0]=t[2]; bf[p*2+1][1]=t[3];
            }
#pragma unroll
            for (int mt = 0; mt < 2; mt++)
#pragma unroll
                for (int nt = 0; nt < 8; nt++)
                    MMA16816(acc[mt][nt], af[mt], bf[nt]);
        }
        slot = (slot + 1 == NSTAGE) ? 0 : slot + 1;
    }

#pragma unroll
    for (int mt = 0; mt < 2; mt++) {
        const int r0g = row0 + wm*32 + mt*16 + (lane >> 2);
#pragma unroll
        for (int nt = 0; nt < 8; nt++) {
            const int col = col0 + wn*64 + nt*8 + (lane & 3)*2;
            const float b0 = bias[col], b1 = bias[col+1];
            float2 v0 = make_float2(acc[mt][nt][0] + b0, acc[mt][nt][1] + b1);
            float2 v1 = make_float2(acc[mt][nt][2] + b0, acc[mt][nt][3] + b1);
            *(float2*)(Cb + (size_t)r0g       * Ntot + col) = v0;
            *(float2*)(Cb + (size_t)(r0g + 8) * Ntot + col) = v1;
        }
    }
}

// ---------------------------------------------------------------------------
// fp32 -> fp16 convert
// ---------------------------------------------------------------------------
__global__ void __launch_bounds__(256)
tohalf_kernel(const float4* __restrict__ src, __half2* __restrict__ dst, int n4)
{
    const int i = blockIdx.x * 256 + threadIdx.x;
    if (i >= n4) return;
    const float4 v = src[i];
    dst[i*2+0] = __floats2half2_rn(v.x, v.y);
    dst[i*2+1] = __floats2half2_rn(v.z, v.w);
}

// g_y (B,D,L) -> g_a (B,L,D) fp16 via 32x32 transpose tiles
__global__ void __launch_bounds__(256)
transhalf_kernel()
{
    __shared__ float t[32][33];
    const int b = blockIdx.z, d0 = blockIdx.y * 32, l0 = blockIdx.x * 32;
    const int tx = threadIdx.x, ty = threadIdx.y;
    for (int dy = ty; dy < 32; dy += 8)
        t[dy][tx] = g_y[((size_t)b * DMODEL + d0 + dy) * LSEQ + l0 + tx];
    __syncthreads();
    for (int ly = ty; ly < 32; ly += 8) {
        const size_t o = ((size_t)b * LSEQ + l0 + ly) * DMODEL + d0 + tx;
        g_a[o] = __float2half_rn(t[tx][ly]);
    }
}

// ---------------------------------------------------------------------------
// Short conv + transpose + gate
// ---------------------------------------------------------------------------
__global__ void __launch_bounds__(256)
shortconv_kernel(const float* __restrict__ sw, const float* __restrict__ sb)
{
    __shared__ float su[3][34][33];
    const int b = blockIdx.z, l0 = blockIdx.x * 32, d0 = blockIdx.y * 32;
    const int tx = threadIdx.x, ty = threadIdx.y;

#pragma unroll
    for (int g = 0; g < 3; g++)
        for (int li = ty; li < 34; li += 8) {
            const int l = l0 + li - 2;
            su[g][li][tx] = (l >= 0)
                ? g_u[((size_t)b * LSEQ + l) * D3 + g * DMODEL + d0 + tx] : 0.f;
        }
    __syncthreads();

    const int l = l0 + tx;
    for (int di = ty; di < 32; di += 8) {
        const int d = d0 + di;
        float r[3];
#pragma unroll
        for (int g = 0; g < 3; g++) {
            const int c = g * DMODEL + d;
            r[g] = sw[c*3+0] * su[g][tx][di]
                 + sw[c*3+1] * su[g][tx+1][di]
                 + sw[c*3+2] * su[g][tx+2][di]
                 + sb[c];
        }
        const size_t o = ((size_t)b * DMODEL + d) * LSEQ + l;
        g_x0[o] = r[0];
        g_vg[o] = r[1] * r[2];
    }
}

// ---------------------------------------------------------------------------
// Filter MLP
// ---------------------------------------------------------------------------
__global__ void __launch_bounds__(256)
filter_h_kernel(const float* __restrict__ w0, const float* __restrict__ b0,
                const float* __restrict__ freq,
                const float* __restrict__ w1, const float* __restrict__ b1,
                const float* __restrict__ w2, const float* __restrict__ b2)
{
    __shared__ float ws[ORDER][ORDER + 1];
    __shared__ float h1[4][ORDER + 1];
    const int o  = threadIdx.x;
    const int lq = threadIdx.y;
    const int l  = blockIdx.x * 4 + lq;
    const int tid = lq * ORDER + o;

    const float t   = (float)l / (float)(LSEQ - 1);
    const float wl  = 2.f * 3.14159265358979323846f * (float)l / (float)LSEQ;
    const float ang = 1e-4f * wl;
    const float z1 = cosf(ang), z2 = -sinf(ang);
    const float fr = freq[o];
    float v = t * w0[o*3+0] + z1 * w0[o*3+1] + z2 * w0[o*3+2] + b0[o];
    h1[lq][o] = sinf(fr * v);
    for (int i = tid; i < ORDER * ORDER; i += 256) ws[i >> 6][i & 63] = w1[i];
    __syncthreads();

    float s = b1[o];
#pragma unroll 8
    for (int j = 0; j < ORDER; j++) s = fmaf(ws[o][j], h1[lq][j], s);
    const float h2v = sinf(fr * s);
    __syncthreads();

    h1[lq][o] = h2v;
    for (int i = tid; i < ORDER * ORDER; i += 256) ws[i >> 6][i & 63] = w2[i];
    __syncthreads();

    s = b2[o];
#pragma unroll 8
    for (int j = 0; j < ORDER; j++) s = fmaf(ws[o][j], h1[lq][j], s);
    g_h[(size_t)l * ORDER + o] = sinf(fr * s);
}

__global__ void __launch_bounds__(256)
filter_k_kernel(const float* __restrict__ w3)
{
    __shared__ float hs[32][ORDER + 1];
    const int l0 = blockIdx.x * 32, d0 = blockIdx.y * 32;
    const int tx = threadIdx.x, ty = threadIdx.y;

    for (int i = ty; i < 32; i += 8) {
        hs[i][tx]      = g_h[(size_t)(l0 + i) * ORDER + tx];
        hs[i][tx + 32] = g_h[(size_t)(l0 + i) * ORDER + tx + 32];
    }
    __syncthreads();

    const int l = l0 + tx;
    const float t = (float)l / (float)(LSEQ - 1);
    const float min_decay = -4.60517018598809136804f / 1.5f;
    const float max_decay = -4.60517018598809136804f / 0.3f;
    for (int di = ty; di < 32; di += 8) {
        const int d = d0 + di;
        float s = 0.f;
#pragma unroll 8
        for (int j = 0; j < ORDER; j++)
            s = fmaf(w3[(size_t)d * ORDER + j], hs[tx][j], s);
        const float delta = min_decay + (max_decay - min_decay) * (float)d / (float)(DMODEL - 1);
        g_k[(size_t)d * LSEQ + l] = s * expf(-t * fabsf(delta));
    }
}

// ---------------------------------------------------------------------------
// N=8192 FFT: three radix-16 register stages + radix-2 tail (XOR swizzle)
// ---------------------------------------------------------------------------
#define SQ(w) ((w) ^ (((w) >> 4) & 15))

__device__ __forceinline__ float2 cmul(float2 a, float2 b) {
    return make_float2(a.x*b.x - a.y*b.y, a.x*b.y + a.y*b.x);
}

__device__ __forceinline__ void fft_init_tw(float2* tw)
{
    for (int i = threadIdx.x; i < 512; i += FFT_T) {
        float s, c;
        sincosf(-2.f * 3.14159265358979323846f * (float)i / (float)NFFT, &s, &c);
        tw[i] = make_float2(c, s);
    }
}

#define CMC(v, wr, wi) do { float _x=(v).x, _y=(v).y; \
    (v).x = _x*(wr) - _y*(wi); (v).y = _x*(wi) + _y*(wr); } while (0)

__device__ __forceinline__ void bf4(float2& a, float2& b, float2& c, float2& d)
{
    const float2 A = make_float2(a.x + c.x, a.y + c.y);
    const float2 B = make_float2(a.x - c.x, a.y - c.y);
    const float2 Cc = make_float2(b.x + d.x, b.y + d.y);
    const float2 D = make_float2(b.x - d.x, b.y - d.y);
    a = make_float2(A.x + Cc.x, A.y + Cc.y);
    c = make_float2(A.x - Cc.x, A.y - Cc.y);
    b = make_float2(B.x + D.y, B.y - D.x);
    d = make_float2(B.x - D.y, B.y + D.x);
}

__device__ __forceinline__ void dft16(float2* x)
{
    bf4(x[0], x[4], x[8],  x[12]);
    bf4(x[1], x[5], x[9],  x[13]);
    bf4(x[2], x[6], x[10], x[14]);
    bf4(x[3], x[7], x[11], x[15]);
    const float C1 = 0.92387953251128674f, S1 = -0.38268343236508978f;
    const float C2 = 0.70710678118654757f, S2 = -0.70710678118654746f;
    const float C3 = 0.38268343236508984f, S3 = -0.92387953251128674f;
    const float C6 = -0.70710678118654746f, S6 = -0.70710678118654757f;
    const float C9 = -0.92387953251128674f, S9 =  0.38268343236508978f;
    CMC(x[5],  C1, S1);  CMC(x[9],  C2, S2);  CMC(x[13], C3, S3);
    CMC(x[6],  C2, S2);  { float tx = x[10].x; x[10].x = x[10].y; x[10].y = -tx; }  CMC(x[14], C6, S6);
    CMC(x[7],  C3, S3);  CMC(x[11], C6, S6);  CMC(x[15], C9, S9);
    bf4(x[0],  x[1],  x[2],  x[3]);
    bf4(x[4],  x[5],  x[6],  x[7]);
    bf4(x[8],  x[9],  x[10], x[11]);
    bf4(x[12], x[13], x[14], x[15]);
}

__device__ __forceinline__ void r16_stage(const float2* __restrict__ src,
                                          float2* __restrict__ dst,
                                          const float2* __restrict__ tw, int m)
{
    const int t = threadIdx.x;
    const int k = t & (m - 1);
    const int jm = t - k;
    float2 x[16];
#pragma unroll
    for (int c = 0; c < 16; c++) x[c] = src[SQ(t + 512 * c)];
    dft16(x);
    const float2 w1 = tw[jm];
    float2 wc = w1;
    const int ob = 16 * jm + k;
    dst[SQ(ob)] = x[0];
#pragma unroll
    for (int c = 1; c < 16; c++) {
        const float2 y = x[((c & 3) << 2) | (c >> 2)];
        dst[SQ(ob + c * m)] = cmul(y, wc);
        wc = cmul(wc, w1);
    }
}

__device__ __forceinline__ float2* fft8192(float2* A, float2* B, const float2* tw)
{
    __syncthreads();
    r16_stage(A, B, tw, 1);    __syncthreads();
    r16_stage(B, A, tw, 16);   __syncthreads();
    r16_stage(A, B, tw, 256);  __syncthreads();
#pragma unroll 1
    for (int i = threadIdx.x; i < 4096; i += FFT_T) {
        const float2 a = B[SQ(i)];
        const float2 b = B[SQ(i + 4096)];
        A[SQ(i)]        = make_float2(a.x + b.x, a.y + b.y);
        A[SQ(i + 4096)] = make_float2(a.x - b.x, a.y - b.y);
    }
    __syncthreads();
    return A;
}

__global__ void fftk_kernel()
{
    extern __shared__ float2 smem_fft[];
    float2* bufA = smem_fft;
    float2* bufB = bufA + NFFT;
    float2* tw   = bufB + NFFT;
    fft_init_tw(tw);

    const int d0 = blockIdx.x * 2;
    const float* k0 = g_k + (size_t)d0 * LSEQ;
    const float* k1 = k0 + LSEQ;
    for (int i = threadIdx.x; i < LSEQ; i += FFT_T) {
        bufA[SQ(i)]        = make_float2(k0[i], k1[i]);
        bufA[SQ(i + LSEQ)] = make_float2(0.f, 0.f);
    }
    float2* Z = fft8192(bufA, bufB, tw);

    const float hc = 0.5f / (float)NFFT;
    float2* o0 = g_Kf + (size_t)d0 * NFFT;
    float2* o1 = o0 + NFFT;
    for (int i = threadIdx.x; i < NFFT; i += FFT_T) {
        const int ir = (NFFT - i) & (NFFT - 1);
        const float2 A = Z[SQ(i)];
        const float2 Zr = Z[SQ(ir)];
        const float sx = A.x + Zr.x, sy = A.y - Zr.y;
        const float px = A.x - Zr.x, py = A.y + Zr.y;
        o0[i] = make_float2(sx * hc, sy * hc);
        o1[i] = make_float2(py * hc, -px * hc);
    }
}

__global__ void fftconv_kernel(const float* __restrict__ fbias)
{
    extern __shared__ float2 smem_fft[];
    float2* bufA = smem_fft;
    float2* bufB = bufA + NFFT;
    float2* tw   = bufB + NFFT;
    fft_init_tw(tw);

    const int d = blockIdx.x;
    const float* v0 = g_vg + (size_t)d * LSEQ;
    const float* v1 = g_vg + ((size_t)DMODEL + d) * LSEQ;

    for (int i = threadIdx.x; i < LSEQ; i += FFT_T) {
        bufA[SQ(i)]        = make_float2(v0[i], v1[i]);
        bufA[SQ(i + LSEQ)] = make_float2(0.f, 0.f);
    }
    float2* Z = fft8192(bufA, bufB, tw);

    const float2* kf = g_Kf + (size_t)d * NFFT;
    for (int i = threadIdx.x; i < NFFT; i += FFT_T) {
        const int ir = (NFFT - i) & (NFFT - 1);
        const float2 A = Z[SQ(i)];
        const float2 Zr = Z[SQ(ir)];
        const float u0x = 0.5f * (A.x + Zr.x), u0y = 0.5f * (A.y - Zr.y);
        const float px  = 0.5f * (A.x - Zr.x), py  = 0.5f * (A.y + Zr.y);
        const float u1x = py, u1y = -px;
        const float2 k = kf[i];
        const float y0x = u0x * k.x - u0y * k.y;
        const float y0y = u0x * k.y + u0y * k.x;
        const float y1x = u1x * k.x - u1y * k.y;
        const float y1y = u1x * k.y + u1y * k.x;
        bufB[SQ(i)] = make_float2(y0x - y1y, -(y0y + y1x));
    }
    float2* out = fft8192(bufB, bufA, tw);

    const float fb = fbias[d];
    for (int i = threadIdx.x; i < LSEQ; i += FFT_T) {
        const size_t o0 = (size_t)d * LSEQ + i;
        const size_t o1 = ((size_t)DMODEL + d) * LSEQ + i;
        const float2 r = out[SQ(i)];
        g_y[o0] = (r.x + v0[i] * fb) * g_x0[o0];
        g_y[o1] = (-r.y + v1[i] * fb) * g_x0[o1];
    }
}

// ---------------------------------------------------------------------------
// Launch
// ---------------------------------------------------------------------------
extern "C" void kernel_launch(void* const* d_in, const int* in_sizes, int n_in,
                              void* d_out, int out_size)
{
    (void)in_sizes; (void)n_in; (void)out_size;
    const float* x     = (const float*)d_in[0];
    const float* ipw   = (const float*)d_in[1];
    const float* ipb   = (const float*)d_in[2];
    const float* sw    = (const float*)d_in[3];
    const float* sb    = (const float*)d_in[4];
    const float* w0    = (const float*)d_in[5];
    const float* b0    = (const float*)d_in[6];
    const float* freq  = (const float*)d_in[7];
    const float* w1    = (const float*)d_in[8];
    const float* b1    = (const float*)d_in[9];
    const float* w2    = (const float*)d_in[10];
    const float* b2    = (const float*)d_in[11];
    const float* w3    = (const float*)d_in[12];
    const float* fbias = (const float*)d_in[13];
    const float* opw   = (const float*)d_in[14];
    const float* opb   = (const float*)d_in[15];
    float* out = (float*)d_out;

    cudaFuncSetAttribute(fftk_kernel,    cudaFuncAttributeMaxDynamicSharedMemorySize, FFT_SMEM);
    cudaFuncSetAttribute(fftconv_kernel, cudaFuncAttributeMaxDynamicSharedMemorySize, FFT_SMEM);
    cudaFuncSetAttribute(gemm_tc_kernel, cudaFuncAttributeMaxDynamicSharedMemorySize, GM_SMEM);

    __half *p_a, *p_w1, *p_w2;
    cudaGetSymbolAddress((void**)&p_a,  g_a);
    cudaGetSymbolAddress((void**)&p_w1, g_w1);
    cudaGetSymbolAddress((void**)&p_w2, g_w2);
    float* p_u; cudaGetSymbolAddress((void**)&p_u, g_u);

    {
        const int n4x = (BATCH*LSEQ*DMODEL)/4;
        tohalf_kernel<<<(n4x+255)/256, 256>>>((const float4*)x, (__half2*)p_a, n4x);
        const int n4w1 = (D3*DMODEL)/4;
        tohalf_kernel<<<(n4w1+255)/256, 256>>>((const float4*)ipw, (__half2*)p_w1, n4w1);
        const int n4w2 = (DMODEL*DMODEL)/4;
        tohalf_kernel<<<(n4w2+255)/256, 256>>>((const float4*)opw, (__half2*)p_w2, n4w2);
    }

    // 1) in_proj GEMM (fp16 HMMA): M=8192, N=6144, K=2048
    gemm_tc_kernel<<<dim3(D3/128, (BATCH*LSEQ)/128, 1), 256, GM_SMEM>>>(
        p_a, p_w1, ipb, p_u, D3, DMODEL, 0, 0);

    // 2) short conv + transpose + gate
    shortconv_kernel<<<dim3(LSEQ/32, DMODEL/32, BATCH), dim3(32, 8)>>>(sw, sb);

    // 3) filter MLP
    filter_h_kernel<<<LSEQ/4, dim3(ORDER, 4)>>>(w0, b0, freq, w1, b1, w2, b2);
    filter_k_kernel<<<dim3(LSEQ/32, DMODEL/32), dim3(32, 8)>>>(w3);

    // 4) FFT of filter k (two channels per block)
    fftk_kernel<<<DMODEL/2, FFT_T, FFT_SMEM>>>();

    // 5) fused FFT conv + bias + output gate (both batches per block)
    fftconv_kernel<<<DMODEL, FFT_T, FFT_SMEM>>>(fbias);

    // 6) transpose y to (B, L, D) fp16
    transhalf_kernel<<<dim3(LSEQ/32, DMODEL/32, BATCH), dim3(32, 8)>>>();

    // 7) out_proj GEMM (fp16 HMMA): per batch M=4096, N=2048, K=2048
    gemm_tc_kernel<<<dim3(DMODEL/128, LSEQ/128, BATCH), 256, GM_SMEM>>>(
        p_a, p_w2, opb, out, DMODEL, DMODEL,
        (size_t)LSEQ*DMODEL, (size_t)LSEQ*DMODEL);
}